// round 1
// baseline (speedup 1.0000x reference)
#include <cuda_runtime.h>
#include <cstdint>

// LSTM: B=32, T=1024, D=1024, H=128  (gates 4H=512, order i,f,g,o)
// out layout: [B*T*H floats][h_n: B*H][c_n: B*H]

#define B_ 32
#define T_ 1024
#define D_ 1024
#define H_ 128
#define G_ 512

typedef unsigned long long u64;

__device__ __forceinline__ u64 pk2(float x, float y) {
    u64 r;
    asm("mov.b64 %0, {%1, %2};" : "=l"(r)
        : "r"(__float_as_uint(x)), "r"(__float_as_uint(y)));
    return r;
}
__device__ __forceinline__ float2 upk2(u64 v) {
    unsigned lo, hi;
    asm("mov.b64 {%0, %1}, %2;" : "=r"(lo), "=r"(hi) : "l"(v));
    return make_float2(__uint_as_float(lo), __uint_as_float(hi));
}
__device__ __forceinline__ void fma2(u64 &c, u64 a, u64 b) {
    asm("fma.rn.f32x2 %0, %1, %2, %0;" : "+l"(c) : "l"(a), "l"(b));
}

__device__ __forceinline__ float fast_sigmoid(float x) {
    return 1.0f / (1.0f + __expf(-x));
}
__device__ __forceinline__ float fast_tanh(float x) {
    // 1 - 2/(e^{2x}+1); saturates correctly for large |x|
    return 1.0f - 2.0f / (__expf(2.0f * x) + 1.0f);
}

// 64 MB scratch for gx = x @ W_ih^T + b  (allocation-free: __device__ global)
__device__ float g_gx[(size_t)B_ * T_ * G_];

// ---------------------------------------------------------------------------
// GEMM: GX[m][n] = sum_k X[m][k] * W[n][k] + b1[n] + b2[n]
// M = 32768, N = 512, K = 1024. Tiles 128x128x16, 256 thr, 8x8/thread, f32x2.
// ---------------------------------------------------------------------------
__global__ __launch_bounds__(256) void gemm_gx(
    const float* __restrict__ X, const float* __restrict__ W,
    const float* __restrict__ b1, const float* __restrict__ b2,
    float* __restrict__ GX)
{
    __shared__ __align__(16) float As[16][132];
    __shared__ __align__(16) float Bs[16][132];

    const int tid  = threadIdx.x;
    const int bm   = blockIdx.x;   // 256 tiles of M
    const int bn   = blockIdx.y;   // 4 tiles of N
    const int rowL = tid >> 1;           // 0..127
    const int colL = (tid & 1) * 8;      // 0 or 8
    const int tx   = tid & 15;
    const int ty   = tid >> 4;

    const float* Ag = X + (size_t)(bm * 128 + rowL) * D_ + colL;
    const float* Bg = W + (size_t)(bn * 128 + rowL) * D_ + colL;

    u64 acc[8][4];
#pragma unroll
    for (int i = 0; i < 8; i++)
#pragma unroll
        for (int j = 0; j < 4; j++) acc[i][j] = pk2(0.0f, 0.0f);

    // preload k-tile 0
    float4 a0 = *(const float4*)(Ag);
    float4 a1 = *(const float4*)(Ag + 4);
    float4 b0 = *(const float4*)(Bg);
    float4 b1f = *(const float4*)(Bg + 4);

    for (int kt = 0; kt < 64; kt++) {
        As[colL + 0][rowL] = a0.x;  As[colL + 1][rowL] = a0.y;
        As[colL + 2][rowL] = a0.z;  As[colL + 3][rowL] = a0.w;
        As[colL + 4][rowL] = a1.x;  As[colL + 5][rowL] = a1.y;
        As[colL + 6][rowL] = a1.z;  As[colL + 7][rowL] = a1.w;
        Bs[colL + 0][rowL] = b0.x;  Bs[colL + 1][rowL] = b0.y;
        Bs[colL + 2][rowL] = b0.z;  Bs[colL + 3][rowL] = b0.w;
        Bs[colL + 4][rowL] = b1f.x; Bs[colL + 5][rowL] = b1f.y;
        Bs[colL + 6][rowL] = b1f.z; Bs[colL + 7][rowL] = b1f.w;
        __syncthreads();

        float4 na0, na1, nb0, nb1;
        if (kt < 63) {
            const float* Ap = Ag + (kt + 1) * 16;
            const float* Bp = Bg + (kt + 1) * 16;
            na0 = *(const float4*)(Ap);
            na1 = *(const float4*)(Ap + 4);
            nb0 = *(const float4*)(Bp);
            nb1 = *(const float4*)(Bp + 4);
        }

#pragma unroll
        for (int k = 0; k < 16; k++) {
            float4 av0 = *(const float4*)&As[k][ty * 8];
            float4 av1 = *(const float4*)&As[k][ty * 8 + 4];
            ulonglong2 bbl = *(const ulonglong2*)&Bs[k][tx * 8];
            ulonglong2 bbh = *(const ulonglong2*)&Bs[k][tx * 8 + 4];
            float a_[8] = {av0.x, av0.y, av0.z, av0.w, av1.x, av1.y, av1.z, av1.w};
#pragma unroll
            for (int i = 0; i < 8; i++) {
                u64 ad = pk2(a_[i], a_[i]);
                fma2(acc[i][0], ad, bbl.x);
                fma2(acc[i][1], ad, bbl.y);
                fma2(acc[i][2], ad, bbh.x);
                fma2(acc[i][3], ad, bbh.y);
            }
        }
        __syncthreads();
        if (kt < 63) { a0 = na0; a1 = na1; b0 = nb0; b1f = nb1; }
    }

    const int m0 = bm * 128 + ty * 8;
    const int n0 = bn * 128 + tx * 8;
    float bias[8];
#pragma unroll
    for (int j = 0; j < 8; j++) bias[j] = b1[n0 + j] + b2[n0 + j];

#pragma unroll
    for (int i = 0; i < 8; i++) {
        float2 u0 = upk2(acc[i][0]);
        float2 u1 = upk2(acc[i][1]);
        float2 u2 = upk2(acc[i][2]);
        float2 u3 = upk2(acc[i][3]);
        float4 v0 = make_float4(u0.x + bias[0], u0.y + bias[1],
                                u1.x + bias[2], u1.y + bias[3]);
        float4 v1 = make_float4(u2.x + bias[4], u2.y + bias[5],
                                u3.x + bias[6], u3.y + bias[7]);
        *(float4*)&GX[(size_t)(m0 + i) * G_ + n0]     = v0;
        *(float4*)&GX[(size_t)(m0 + i) * G_ + n0 + 4] = v1;
    }
}

// ---------------------------------------------------------------------------
// Recurrence: one CTA per batch element, 512 threads (thread t = gate row t).
// W_hh split: j=0..95 in smem as [jblk][512 rows][4] (coalesced LDS.128),
//             j=96..127 in registers (16 x u64 per thread).
// Per step: 512-row x 128 gemv via f32x2, per-thread activation, 128-thread
// combine for c/h, 2 barriers. FMA-pipe bound ~650 cyc/step.
// ---------------------------------------------------------------------------
#define JB_SMEM 24   // 24 blocks of 4 -> j = 0..95 in smem (192 KB)

__global__ __launch_bounds__(512, 1) void lstm_rec(
    const float* __restrict__ GX, const float* __restrict__ Wh,
    float* __restrict__ out, float* __restrict__ hn, float* __restrict__ cn)
{
    extern __shared__ __align__(16) float sm[];
    float* Wsm = sm;                          // [24][512][4] = 49152 floats
    float* h_s = sm + JB_SMEM * 512 * 4;      // [128]
    float* act = h_s + 128;                   // [512]

    const int tid = threadIdx.x;
    const int b   = blockIdx.x;

    // Stage smem weights: Wsm[jb*512 + r][0..3] = Wh[r][jb*4 .. jb*4+3]
    for (int idx = tid; idx < JB_SMEM * 512; idx += 512) {
        int jb = idx >> 9, r = idx & 511;
        *(float4*)&Wsm[(size_t)idx * 4] = *(const float4*)&Wh[(size_t)r * H_ + jb * 4];
    }
    // Register weights: j = 96..127 of own row
    u64 wreg[16];
#pragma unroll
    for (int i = 0; i < 8; i++) {
        ulonglong2 w = *(const ulonglong2*)&Wh[(size_t)tid * H_ + 96 + i * 4];
        wreg[2 * i]     = w.x;
        wreg[2 * i + 1] = w.y;
    }
    if (tid < H_) h_s[tid] = 0.0f;
    float cst = 0.0f;
    __syncthreads();

    const float* gxb  = GX + (size_t)b * T_ * G_;
    float* outb       = out + (size_t)b * T_ * H_;
    const bool is_tanh_gate = ((tid >> 7) == 2);   // gate 'g'

    for (int t = 0; t < T_; t++) {
        float gval = __ldg(&gxb[(size_t)t * G_ + tid]);   // hidden under FMA loop

        u64 acc0 = pk2(0.0f, 0.0f), acc1 = pk2(0.0f, 0.0f);
        const ulonglong2* h64 = (const ulonglong2*)h_s;
#pragma unroll
        for (int jb = 0; jb < JB_SMEM; jb++) {
            ulonglong2 hh = h64[jb];
            ulonglong2 ww = *(const ulonglong2*)&Wsm[(size_t)(jb * 512 + tid) * 4];
            fma2(acc0, hh.x, ww.x);
            fma2(acc1, hh.y, ww.y);
        }
#pragma unroll
        for (int i = 0; i < 8; i++) {
            ulonglong2 hh = h64[JB_SMEM + i];
            fma2(acc0, hh.x, wreg[2 * i]);
            fma2(acc1, hh.y, wreg[2 * i + 1]);
        }
        float2 u0 = upk2(acc0), u1 = upk2(acc1);
        float g = (u0.x + u0.y) + (u1.x + u1.y) + gval;

        act[tid] = is_tanh_gate ? fast_tanh(g) : fast_sigmoid(g);
        __syncthreads();

        if (tid < H_) {
            float ig = act[tid];
            float fg = act[H_ + tid];
            float gg = act[2 * H_ + tid];
            float og = act[3 * H_ + tid];
            cst = fg * cst + ig * gg;
            float hv = og * fast_tanh(cst);
            h_s[tid] = hv;
            outb[(size_t)t * H_ + tid] = hv;
        }
        __syncthreads();
    }

    if (tid < H_) {
        hn[b * H_ + tid] = h_s[tid];
        cn[b * H_ + tid] = cst;
    }
}

// ---------------------------------------------------------------------------
extern "C" void kernel_launch(void* const* d_in, const int* in_sizes, int n_in,
                              void* d_out, int out_size)
{
    const float* x   = (const float*)d_in[0];
    const float* Wih = (const float*)d_in[1];
    const float* Whh = (const float*)d_in[2];
    const float* bih = (const float*)d_in[3];
    const float* bhh = (const float*)d_in[4];
    float* out = (float*)d_out;

    float* gx = nullptr;
    cudaGetSymbolAddress((void**)&gx, g_gx);

    dim3 grid(256, 4);
    gemm_gx<<<grid, 256>>>(x, Wih, bih, bhh, gx);

    size_t smem = (size_t)(JB_SMEM * 512 * 4 + 128 + 512) * sizeof(float); // 199168 B
    cudaFuncSetAttribute(lstm_rec, cudaFuncAttributeMaxDynamicSharedMemorySize, (int)smem);

    float* hn = out + (size_t)B_ * T_ * H_;
    float* cn = hn + (size_t)B_ * H_;
    lstm_rec<<<B_, 512, smem>>>(gx, Whh, out, hn, cn);
}

// round 2
// speedup vs baseline: 1.2251x; 1.2251x over previous
#include <cuda_runtime.h>
#include <cstdint>

// LSTM: B=32, T=1024, D=1024, H=128  (gates 4H=512, order i,f,g,o)
// out layout: [B*T*H floats][h_n: B*H][c_n: B*H]

#define B_ 32
#define T_ 1024
#define D_ 1024
#define H_ 128
#define G_ 512

typedef unsigned long long u64;

__device__ __forceinline__ u64 pk2(float x, float y) {
    u64 r;
    asm("mov.b64 %0, {%1, %2};" : "=l"(r)
        : "r"(__float_as_uint(x)), "r"(__float_as_uint(y)));
    return r;
}
__device__ __forceinline__ float2 upk2(u64 v) {
    unsigned lo, hi;
    asm("mov.b64 {%0, %1}, %2;" : "=r"(lo), "=r"(hi) : "l"(v));
    return make_float2(__uint_as_float(lo), __uint_as_float(hi));
}
__device__ __forceinline__ void fma2(u64 &c, u64 a, u64 b) {
    asm("fma.rn.f32x2 %0, %1, %2, %0;" : "+l"(c) : "l"(a), "l"(b));
}

__device__ __forceinline__ float fast_sigmoid(float x) {
    return 1.0f / (1.0f + __expf(-x));
}
__device__ __forceinline__ float fast_tanh(float x) {
    return 1.0f - 2.0f / (__expf(2.0f * x) + 1.0f);
}

__device__ __forceinline__ uint32_t smem_u32(const void* p) {
    uint32_t a;
    asm("{ .reg .u64 t; cvta.to.shared.u64 t, %1; cvt.u32.u64 %0, t; }"
        : "=r"(a) : "l"(p));
    return a;
}

// 64 MB scratch for gx = x @ W_ih^T + b  (allocation-free: __device__ global)
__device__ float g_gx[(size_t)B_ * T_ * G_];

// ---------------------------------------------------------------------------
// GEMM: GX[m][n] = sum_k X[m][k] * W[n][k] + b1[n] + b2[n]
// M = 32768, N = 512, K = 1024. Tiles 128x128x16, 256 thr, 8x8/thread, f32x2.
// ---------------------------------------------------------------------------
__global__ __launch_bounds__(256) void gemm_gx(
    const float* __restrict__ X, const float* __restrict__ W,
    const float* __restrict__ b1, const float* __restrict__ b2,
    float* __restrict__ GX)
{
    __shared__ __align__(16) float As[16][132];
    __shared__ __align__(16) float Bs[16][132];

    const int tid  = threadIdx.x;
    const int bm   = blockIdx.x;   // 256 tiles of M
    const int bn   = blockIdx.y;   // 4 tiles of N
    const int rowL = tid >> 1;           // 0..127
    const int colL = (tid & 1) * 8;      // 0 or 8
    const int tx   = tid & 15;
    const int ty   = tid >> 4;

    const float* Ag = X + (size_t)(bm * 128 + rowL) * D_ + colL;
    const float* Bg = W + (size_t)(bn * 128 + rowL) * D_ + colL;

    u64 acc[8][4];
#pragma unroll
    for (int i = 0; i < 8; i++)
#pragma unroll
        for (int j = 0; j < 4; j++) acc[i][j] = pk2(0.0f, 0.0f);

    float4 a0 = *(const float4*)(Ag);
    float4 a1 = *(const float4*)(Ag + 4);
    float4 b0 = *(const float4*)(Bg);
    float4 b1f = *(const float4*)(Bg + 4);

    for (int kt = 0; kt < 64; kt++) {
        As[colL + 0][rowL] = a0.x;  As[colL + 1][rowL] = a0.y;
        As[colL + 2][rowL] = a0.z;  As[colL + 3][rowL] = a0.w;
        As[colL + 4][rowL] = a1.x;  As[colL + 5][rowL] = a1.y;
        As[colL + 6][rowL] = a1.z;  As[colL + 7][rowL] = a1.w;
        Bs[colL + 0][rowL] = b0.x;  Bs[colL + 1][rowL] = b0.y;
        Bs[colL + 2][rowL] = b0.z;  Bs[colL + 3][rowL] = b0.w;
        Bs[colL + 4][rowL] = b1f.x; Bs[colL + 5][rowL] = b1f.y;
        Bs[colL + 6][rowL] = b1f.z; Bs[colL + 7][rowL] = b1f.w;
        __syncthreads();

        float4 na0, na1, nb0, nb1;
        if (kt < 63) {
            const float* Ap = Ag + (kt + 1) * 16;
            const float* Bp = Bg + (kt + 1) * 16;
            na0 = *(const float4*)(Ap);
            na1 = *(const float4*)(Ap + 4);
            nb0 = *(const float4*)(Bp);
            nb1 = *(const float4*)(Bp + 4);
        }

#pragma unroll
        for (int k = 0; k < 16; k++) {
            float4 av0 = *(const float4*)&As[k][ty * 8];
            float4 av1 = *(const float4*)&As[k][ty * 8 + 4];
            ulonglong2 bbl = *(const ulonglong2*)&Bs[k][tx * 8];
            ulonglong2 bbh = *(const ulonglong2*)&Bs[k][tx * 8 + 4];
            float a_[8] = {av0.x, av0.y, av0.z, av0.w, av1.x, av1.y, av1.z, av1.w};
#pragma unroll
            for (int i = 0; i < 8; i++) {
                u64 ad = pk2(a_[i], a_[i]);
                fma2(acc[i][0], ad, bbl.x);
                fma2(acc[i][1], ad, bbl.y);
                fma2(acc[i][2], ad, bbh.x);
                fma2(acc[i][3], ad, bbh.y);
            }
        }
        __syncthreads();
        if (kt < 63) { a0 = na0; a1 = na1; b0 = nb0; b1f = nb1; }
    }

    const int m0 = bm * 128 + ty * 8;
    const int n0 = bn * 128 + tx * 8;
    float bias[8];
#pragma unroll
    for (int j = 0; j < 8; j++) bias[j] = b1[n0 + j] + b2[n0 + j];

#pragma unroll
    for (int i = 0; i < 8; i++) {
        float2 u0 = upk2(acc[i][0]);
        float2 u1 = upk2(acc[i][1]);
        float2 u2 = upk2(acc[i][2]);
        float2 u3 = upk2(acc[i][3]);
        float4 v0 = make_float4(u0.x + bias[0], u0.y + bias[1],
                                u1.x + bias[2], u1.y + bias[3]);
        float4 v1 = make_float4(u2.x + bias[4], u2.y + bias[5],
                                u3.x + bias[6], u3.y + bias[7]);
        *(float4*)&GX[(size_t)(m0 + i) * G_ + n0]     = v0;
        *(float4*)&GX[(size_t)(m0 + i) * G_ + n0 + 4] = v1;
    }
}

// ---------------------------------------------------------------------------
// Recurrence v2: 2-CTA cluster per batch element. Weights fully register-
// resident (64 floats/thread). h read via conflict-free broadcast LDS.128.
// Gate exchange via st.shared::cluster into double-buffered acts + one
// barrier.cluster per step. Both CTAs redundantly compute c/h.
// ---------------------------------------------------------------------------
__global__ __launch_bounds__(512, 1) __cluster_dims__(2, 1, 1)
void lstm_rec2(const float* __restrict__ GX, const float* __restrict__ Wh,
               float* __restrict__ out, float* __restrict__ hn,
               float* __restrict__ cn)
{
    __shared__ __align__(16) float h_s[128];
    __shared__ __align__(16) float acts[2][512];

    const int tid = threadIdx.x;
    uint32_t rank;
    asm("mov.u32 %0, %%cluster_ctarank;" : "=r"(rank));
    const int b    = blockIdx.x >> 1;
    const int row  = tid >> 1;            // 0..255 local row
    const int p    = tid & 1;             // K-half interleave parity
    const int grow = (int)rank * 256 + row;

    // Register weights: thread covers 16-byte chunks c = p, p+2, ..., p+30
    // of W_hh row `grow` (64 floats = 32 u64 = 64 regs).
    u64 wa[16], wb[16];
#pragma unroll
    for (int m = 0; m < 16; m++) {
        const float4 w = *(const float4*)&Wh[(size_t)grow * H_ + (p + 2 * m) * 4];
        wa[m] = pk2(w.x, w.y);
        wb[m] = pk2(w.z, w.w);
    }

    if (tid < H_) h_s[tid] = 0.0f;
    float cst = 0.0f;
    const bool is_tanh = (rank == 1) && (row < 128);   // gate 'g' rows 256..383

    const float* gxb  = GX + (size_t)b * T_ * G_;
    float* outb       = out + (size_t)b * T_ * H_;

    // Peer-CTA addresses of acts[buf][grow]
    uint32_t peer0, peer1;
    {
        uint32_t l0 = smem_u32(&acts[0][grow]);
        uint32_t l1 = smem_u32(&acts[1][grow]);
        asm("mapa.shared::cluster.u32 %0, %1, %2;" : "=r"(peer0) : "r"(l0), "r"(rank ^ 1u));
        asm("mapa.shared::cluster.u32 %0, %1, %2;" : "=r"(peer1) : "r"(l1), "r"(rank ^ 1u));
    }

    float gxv = (p == 0) ? __ldg(&gxb[grow]) : 0.0f;

    // one-time cluster sync: smem init + cluster residency
    asm volatile("barrier.cluster.arrive.aligned;" ::: "memory");
    asm volatile("barrier.cluster.wait.aligned;" ::: "memory");

    for (int t = 0; t < T_; t++) {
        const int buf = t & 1;

        // gemv partial: 32 packed FMAs against register weights
        u64 acc0 = pk2(0.0f, 0.0f), acc1 = pk2(0.0f, 0.0f);
        const ulonglong2* h2 = (const ulonglong2*)h_s;   // chunk c -> h2[c]
#pragma unroll
        for (int m = 0; m < 16; m++) {
            ulonglong2 hh = h2[p + 2 * m];
            fma2(acc0, hh.x, wa[m]);
            fma2(acc1, hh.y, wb[m]);
        }
        float2 u0 = upk2(acc0), u1 = upk2(acc1);
        float s = (u0.x + u0.y) + (u1.x + u1.y);
        s += __shfl_xor_sync(0xffffffffu, s, 1);

        if (p == 0) {
            float g = s + gxv;
            float a = is_tanh ? fast_tanh(g) : fast_sigmoid(g);
            acts[buf][grow] = a;
            uint32_t pa = buf ? peer1 : peer0;
            asm volatile("st.shared::cluster.f32 [%0], %1;" :: "r"(pa), "f"(a));
            if (t + 1 < T_) gxv = __ldg(&gxb[(size_t)(t + 1) * G_ + grow]);
        }

        // publish gates both ways (release/acquire across the cluster)
        asm volatile("barrier.cluster.arrive.aligned;" ::: "memory");
        asm volatile("barrier.cluster.wait.aligned;" ::: "memory");

        if (tid < H_) {
            float ig = acts[buf][tid];
            float fg = acts[buf][H_ + tid];
            float gg = acts[buf][2 * H_ + tid];
            float og = acts[buf][3 * H_ + tid];
            cst = fg * cst + ig * gg;
            float hv = og * fast_tanh(cst);
            h_s[tid] = hv;
            if (rank == 0) outb[(size_t)t * H_ + tid] = hv;
        }
        __syncthreads();   // h_s ready for next step's gemv
    }

    if (rank == 0 && tid < H_) {
        hn[b * H_ + tid] = h_s[tid];
        cn[b * H_ + tid] = cst;
    }
}

// ---------------------------------------------------------------------------
extern "C" void kernel_launch(void* const* d_in, const int* in_sizes, int n_in,
                              void* d_out, int out_size)
{
    const float* x   = (const float*)d_in[0];
    const float* Wih = (const float*)d_in[1];
    const float* Whh = (const float*)d_in[2];
    const float* bih = (const float*)d_in[3];
    const float* bhh = (const float*)d_in[4];
    float* out = (float*)d_out;

    float* gx = nullptr;
    cudaGetSymbolAddress((void**)&gx, g_gx);

    dim3 grid(256, 4);
    gemm_gx<<<grid, 256>>>(x, Wih, bih, bhh, gx);

    float* hn = out + (size_t)B_ * T_ * H_;
    float* cn = hn + (size_t)B_ * H_;
    lstm_rec2<<<B_ * 2, 512>>>(gx, Whh, out, hn, cn);
}

// round 3
// speedup vs baseline: 1.4361x; 1.1722x over previous
#include <cuda_runtime.h>
#include <cstdint>

// LSTM: B=32, T=1024, D=1024, H=128  (gates 4H=512, order i,f,g,o)
// out layout: [B*T*H floats][h_n: B*H][c_n: B*H]

#define B_ 32
#define T_ 1024
#define D_ 1024
#define H_ 128
#define G_ 512

typedef unsigned long long u64;

__device__ __forceinline__ u64 pk2(float x, float y) {
    u64 r;
    asm("mov.b64 %0, {%1, %2};" : "=l"(r)
        : "r"(__float_as_uint(x)), "r"(__float_as_uint(y)));
    return r;
}
__device__ __forceinline__ float2 upk2(u64 v) {
    unsigned lo, hi;
    asm("mov.b64 {%0, %1}, %2;" : "=r"(lo), "=r"(hi) : "l"(v));
    return make_float2(__uint_as_float(lo), __uint_as_float(hi));
}
__device__ __forceinline__ void fma2(u64 &c, u64 a, u64 b) {
    asm("fma.rn.f32x2 %0, %1, %2, %0;" : "+l"(c) : "l"(a), "l"(b));
}

__device__ __forceinline__ float fast_sigmoid(float x) {
    return 1.0f / (1.0f + __expf(-x));
}
__device__ __forceinline__ float fast_tanh(float x) {
    return 1.0f - 2.0f / (__expf(2.0f * x) + 1.0f);
}

__device__ __forceinline__ uint32_t smem_u32(const void* p) {
    uint32_t a;
    asm("{ .reg .u64 t; cvta.to.shared.u64 t, %1; cvt.u32.u64 %0, t; }"
        : "=r"(a) : "l"(p));
    return a;
}

// 64 MB scratch for gx = x @ W_ih^T + b  (allocation-free: __device__ global)
__device__ float g_gx[(size_t)B_ * T_ * G_];

// ---------------------------------------------------------------------------
// GEMM: GX[m][n] = sum_k X[m][k] * W[n][k] + b1[n] + b2[n]
// M = 32768, N = 512, K = 1024. Tiles 128x128x16, 256 thr, 8x8/thread, f32x2.
// ---------------------------------------------------------------------------
__global__ __launch_bounds__(256) void gemm_gx(
    const float* __restrict__ X, const float* __restrict__ W,
    const float* __restrict__ b1, const float* __restrict__ b2,
    float* __restrict__ GX)
{
    __shared__ __align__(16) float As[16][132];
    __shared__ __align__(16) float Bs[16][132];

    const int tid  = threadIdx.x;
    const int bm   = blockIdx.x;
    const int bn   = blockIdx.y;
    const int rowL = tid >> 1;
    const int colL = (tid & 1) * 8;
    const int tx   = tid & 15;
    const int ty   = tid >> 4;

    const float* Ag = X + (size_t)(bm * 128 + rowL) * D_ + colL;
    const float* Bg = W + (size_t)(bn * 128 + rowL) * D_ + colL;

    u64 acc[8][4];
#pragma unroll
    for (int i = 0; i < 8; i++)
#pragma unroll
        for (int j = 0; j < 4; j++) acc[i][j] = pk2(0.0f, 0.0f);

    float4 a0 = *(const float4*)(Ag);
    float4 a1 = *(const float4*)(Ag + 4);
    float4 b0 = *(const float4*)(Bg);
    float4 b1f = *(const float4*)(Bg + 4);

    for (int kt = 0; kt < 64; kt++) {
        As[colL + 0][rowL] = a0.x;  As[colL + 1][rowL] = a0.y;
        As[colL + 2][rowL] = a0.z;  As[colL + 3][rowL] = a0.w;
        As[colL + 4][rowL] = a1.x;  As[colL + 5][rowL] = a1.y;
        As[colL + 6][rowL] = a1.z;  As[colL + 7][rowL] = a1.w;
        Bs[colL + 0][rowL] = b0.x;  Bs[colL + 1][rowL] = b0.y;
        Bs[colL + 2][rowL] = b0.z;  Bs[colL + 3][rowL] = b0.w;
        Bs[colL + 4][rowL] = b1f.x; Bs[colL + 5][rowL] = b1f.y;
        Bs[colL + 6][rowL] = b1f.z; Bs[colL + 7][rowL] = b1f.w;
        __syncthreads();

        float4 na0, na1, nb0, nb1;
        if (kt < 63) {
            const float* Ap = Ag + (kt + 1) * 16;
            const float* Bp = Bg + (kt + 1) * 16;
            na0 = *(const float4*)(Ap);
            na1 = *(const float4*)(Ap + 4);
            nb0 = *(const float4*)(Bp);
            nb1 = *(const float4*)(Bp + 4);
        }

#pragma unroll
        for (int k = 0; k < 16; k++) {
            float4 av0 = *(const float4*)&As[k][ty * 8];
            float4 av1 = *(const float4*)&As[k][ty * 8 + 4];
            ulonglong2 bbl = *(const ulonglong2*)&Bs[k][tx * 8];
            ulonglong2 bbh = *(const ulonglong2*)&Bs[k][tx * 8 + 4];
            float a_[8] = {av0.x, av0.y, av0.z, av0.w, av1.x, av1.y, av1.z, av1.w};
#pragma unroll
            for (int i = 0; i < 8; i++) {
                u64 ad = pk2(a_[i], a_[i]);
                fma2(acc[i][0], ad, bbl.x);
                fma2(acc[i][1], ad, bbl.y);
                fma2(acc[i][2], ad, bbh.x);
                fma2(acc[i][3], ad, bbh.y);
            }
        }
        __syncthreads();
        if (kt < 63) { a0 = na0; a1 = na1; b0 = nb0; b1f = nb1; }
    }

    const int m0 = bm * 128 + ty * 8;
    const int n0 = bn * 128 + tx * 8;
    float bias[8];
#pragma unroll
    for (int j = 0; j < 8; j++) bias[j] = b1[n0 + j] + b2[n0 + j];

#pragma unroll
    for (int i = 0; i < 8; i++) {
        float2 u0 = upk2(acc[i][0]);
        float2 u1 = upk2(acc[i][1]);
        float2 u2 = upk2(acc[i][2]);
        float2 u3 = upk2(acc[i][3]);
        float4 v0 = make_float4(u0.x + bias[0], u0.y + bias[1],
                                u1.x + bias[2], u1.y + bias[3]);
        float4 v1 = make_float4(u2.x + bias[4], u2.y + bias[5],
                                u3.x + bias[6], u3.y + bias[7]);
        *(float4*)&GX[(size_t)(m0 + i) * G_ + n0]     = v0;
        *(float4*)&GX[(size_t)(m0 + i) * G_ + n0 + 4] = v1;
    }
}

// ---------------------------------------------------------------------------
// Recurrence v3: 2-CTA cluster per batch. Each CTA owns ALL 4 gates for 64
// h-indices -> c/h update is fully local. Only the 64 new h values cross the
// cluster, via st.async + mbarrier complete_tx (single DSMEM message), with
// double-buffered h and parity waits. gemv splits own-half (before wait) /
// peer-half (after wait) to hide DSMEM latency. No barrier.cluster in loop.
// ---------------------------------------------------------------------------
__global__ __launch_bounds__(512, 1) __cluster_dims__(2, 1, 1)
void lstm_rec3(const float* __restrict__ GX, const float* __restrict__ Wh,
               float* __restrict__ out, float* __restrict__ hn,
               float* __restrict__ cn)
{
    __shared__ __align__(16) float hbuf[2][128];
    __shared__ __align__(16) float acts[256];
    __shared__ __align__(8) unsigned long long mbar[2];

    const int tid = threadIdx.x;
    uint32_t rank;
    asm("mov.u32 %0, %%cluster_ctarank;" : "=r"(rank));
    const int b    = blockIdx.x >> 1;
    const int rl   = tid >> 1;            // 0..255: local row = q*64 + j
    const int p    = tid & 1;             // K-half parity
    const int q    = rl >> 6;             // gate 0..3 (i,f,g,o)
    const int j    = rl & 63;             // local h index
    const int grow = q * 128 + (int)rank * 64 + j;  // global gate row
    const int base = (int)rank * 8;       // own-half chunk rotation

    // Register weights, rotated so m=0..7 hit the OWN h-half first.
    // chunk c covers h[4c..4c+3]; thread holds c = p + 2*((base+m)&15).
    u64 wa[16], wb[16];
#pragma unroll
    for (int m = 0; m < 16; m++) {
        int c = p + 2 * ((base + m) & 15);
        float4 w = *(const float4*)&Wh[(size_t)grow * H_ + c * 4];
        wa[m] = pk2(w.x, w.y);
        wb[m] = pk2(w.z, w.w);
    }

    if (tid < 128) { hbuf[0][tid] = 0.0f; hbuf[1][tid] = 0.0f; }
    uint32_t mb_loc0 = smem_u32(&mbar[0]);
    uint32_t mb_loc1 = smem_u32(&mbar[1]);
    if (tid == 0) {
        asm volatile("mbarrier.init.shared.b64 [%0], 1;" :: "r"(mb_loc0) : "memory");
        asm volatile("mbarrier.init.shared.b64 [%0], 1;" :: "r"(mb_loc1) : "memory");
        // pre-arm both barriers for their first use (64 x 4B = 256 bytes)
        asm volatile("mbarrier.arrive.expect_tx.shared.b64 _, [%0], 256;" :: "r"(mb_loc0) : "memory");
        asm volatile("mbarrier.arrive.expect_tx.shared.b64 _, [%0], 256;" :: "r"(mb_loc1) : "memory");
    }

    // Peer addresses for this thread's h slot (producers: tid<64) + peer mbars.
    uint32_t ph_peer0, ph_peer1, pm_peer0, pm_peer1;
    {
        const uint32_t r_ = rank ^ 1u;
        int hid = (int)rank * 64 + (tid & 63);
        uint32_t l0 = smem_u32(&hbuf[0][hid]);
        uint32_t l1 = smem_u32(&hbuf[1][hid]);
        asm("mapa.shared::cluster.u32 %0, %1, %2;" : "=r"(ph_peer0) : "r"(l0), "r"(r_));
        asm("mapa.shared::cluster.u32 %0, %1, %2;" : "=r"(ph_peer1) : "r"(l1), "r"(r_));
        asm("mapa.shared::cluster.u32 %0, %1, %2;" : "=r"(pm_peer0) : "r"(mb_loc0), "r"(r_));
        asm("mapa.shared::cluster.u32 %0, %1, %2;" : "=r"(pm_peer1) : "r"(mb_loc1), "r"(r_));
    }

    const float* gxb = GX + (size_t)b * T_ * G_;
    float* outb      = out + (size_t)b * T_ * H_;
    float gxv = (p == 0) ? __ldg(&gxb[grow]) : 0.0f;
    float cst = 0.0f;
    int ph0 = 0, ph1 = 0;

    // one-time cluster sync: mbarrier init + smem zero visible cluster-wide
    asm volatile("barrier.cluster.arrive.aligned;" ::: "memory");
    asm volatile("barrier.cluster.wait.aligned;" ::: "memory");

    for (int t = 0; t < T_; t++) {
        const int cb = t & 1, nb = cb ^ 1;
        const ulonglong2* h2 = (const ulonglong2*)hbuf[cb];

        u64 acc0 = pk2(0.0f, 0.0f), acc1 = pk2(0.0f, 0.0f);
        // own-half: h values produced locally last step (already visible)
#pragma unroll
        for (int m = 0; m < 8; m++) {
            ulonglong2 hh = h2[p + 2 * ((base + m) & 15)];
            fma2(acc0, hh.x, wa[m]);
            fma2(acc1, hh.y, wb[m]);
        }
        // wait for peer half of h(t)
        if (t > 0) {
            uint32_t mb = cb ? mb_loc1 : mb_loc0;
            int par = cb ? ph1 : ph0;
            asm volatile(
                "{\n\t.reg .pred P;\n\t"
                "WL%=:\n\t"
                "mbarrier.try_wait.parity.acquire.cluster.shared::cta.b64 P, [%0], %1, 0x989680;\n\t"
                "@P bra WD%=;\n\t"
                "bra WL%=;\n\t"
                "WD%=:\n\t}"
                :: "r"(mb), "r"(par) : "memory");
            if (cb) ph1 ^= 1; else ph0 ^= 1;
            if (tid == 0)  // re-arm for next use (2 steps away; safe by ordering)
                asm volatile("mbarrier.arrive.expect_tx.shared.b64 _, [%0], 256;"
                             :: "r"(mb) : "memory");
        }
        // peer-half
#pragma unroll
        for (int m = 8; m < 16; m++) {
            ulonglong2 hh = h2[p + 2 * ((base + m) & 15)];
            fma2(acc0, hh.x, wa[m]);
            fma2(acc1, hh.y, wb[m]);
        }
        float2 u0 = upk2(acc0), u1 = upk2(acc1);
        float s = (u0.x + u0.y) + (u1.x + u1.y);
        s += __shfl_xor_sync(0xffffffffu, s, 1);

        if (p == 0) {
            float g = s + gxv;
            acts[rl] = (q == 2) ? fast_tanh(g) : fast_sigmoid(g);
            if (t + 1 < T_) gxv = __ldg(&gxb[(size_t)(t + 1) * G_ + grow]);
        }
        __syncthreads();

        if (tid < 64) {
            float ig = acts[tid];
            float fg = acts[64 + tid];
            float gg = acts[128 + tid];
            float og = acts[192 + tid];
            cst = fg * cst + ig * gg;
            float hv = og * fast_tanh(cst);
            const int hid = (int)rank * 64 + tid;
            hbuf[nb][hid] = hv;
            {
                uint32_t pa = nb ? ph_peer1 : ph_peer0;
                uint32_t pm = nb ? pm_peer1 : pm_peer0;
                asm volatile(
                    "st.async.shared::cluster.mbarrier::complete_tx::bytes.b32 [%0], %1, [%2];"
                    :: "r"(pa), "r"(__float_as_uint(hv)), "r"(pm) : "memory");
            }
            outb[(size_t)t * H_ + hid] = hv;
            if (t == T_ - 1) {
                hn[b * H_ + hid] = hv;
                cn[b * H_ + hid] = cst;
            }
        }
        __syncthreads();
    }
}

// ---------------------------------------------------------------------------
extern "C" void kernel_launch(void* const* d_in, const int* in_sizes, int n_in,
                              void* d_out, int out_size)
{
    const float* x   = (const float*)d_in[0];
    const float* Wih = (const float*)d_in[1];
    const float* Whh = (const float*)d_in[2];
    const float* bih = (const float*)d_in[3];
    const float* bhh = (const float*)d_in[4];
    float* out = (float*)d_out;

    float* gx = nullptr;
    cudaGetSymbolAddress((void**)&gx, g_gx);

    dim3 grid(256, 4);
    gemm_gx<<<grid, 256>>>(x, Wih, bih, bhh, gx);

    float* hn = out + (size_t)B_ * T_ * H_;
    float* cn = hn + (size_t)B_ * H_;
    lstm_rec3<<<B_ * 2, 512>>>(gx, Whh, out, hn, cn);
}

// round 7
// speedup vs baseline: 1.5180x; 1.0570x over previous
#include <cuda_runtime.h>
#include <cuda_bf16.h>
#include <cstdint>

// LSTM: B=32, T=1024, D=1024, H=128  (gates 4H=512, order i,f,g,o)
// out layout: [B*T*H floats][h_n: B*H][c_n: B*H]

#define B_ 32
#define T_ 1024
#define D_ 1024
#define H_ 128
#define G_ 512

typedef unsigned long long u64;

__device__ __forceinline__ u64 pk2(float x, float y) {
    u64 r;
    asm("mov.b64 %0, {%1, %2};" : "=l"(r)
        : "r"(__float_as_uint(x)), "r"(__float_as_uint(y)));
    return r;
}
__device__ __forceinline__ float2 upk2(u64 v) {
    unsigned lo, hi;
    asm("mov.b64 {%0, %1}, %2;" : "=r"(lo), "=r"(hi) : "l"(v));
    return make_float2(__uint_as_float(lo), __uint_as_float(hi));
}
__device__ __forceinline__ void fma2(u64 &c, u64 a, u64 b) {
    asm("fma.rn.f32x2 %0, %1, %2, %0;" : "+l"(c) : "l"(a), "l"(b));
}
__device__ __forceinline__ float fast_sigmoid(float x) {
    return 1.0f / (1.0f + __expf(-x));
}
__device__ __forceinline__ float fast_tanh(float x) {
    return 1.0f - 2.0f / (__expf(2.0f * x) + 1.0f);
}
__device__ __forceinline__ uint32_t smem_u32(const void* p) {
    uint32_t a;
    asm("{ .reg .u64 t; cvta.to.shared.u64 t, %1; cvt.u32.u64 %0, t; }"
        : "=r"(a) : "l"(p));
    return a;
}
__device__ __forceinline__ void cp16(uint32_t dst, const void* src) {
    asm volatile("cp.async.cg.shared.global [%0], [%1], 16;"
                 :: "r"(dst), "l"(src));
}
__device__ __forceinline__ void ldsm4(uint32_t* r, uint32_t addr) {
    asm volatile("ldmatrix.sync.aligned.m8n8.x4.shared.b16 {%0,%1,%2,%3}, [%4];"
                 : "=r"(r[0]), "=r"(r[1]), "=r"(r[2]), "=r"(r[3]) : "r"(addr));
}
__device__ __forceinline__ void mma16816(float* d, const uint32_t* a,
                                         uint32_t b0, uint32_t b1) {
    asm volatile(
        "mma.sync.aligned.m16n8k16.row.col.f32.bf16.bf16.f32 "
        "{%0,%1,%2,%3}, {%4,%5,%6,%7}, {%8,%9}, {%0,%1,%2,%3};"
        : "+f"(d[0]), "+f"(d[1]), "+f"(d[2]), "+f"(d[3])
        : "r"(a[0]), "r"(a[1]), "r"(a[2]), "r"(a[3]), "r"(b0), "r"(b1));
}

// Scratch (__device__ globals: allocation-free)
__device__ float g_gx[(size_t)B_ * T_ * G_];                 // 64 MB
__device__ __nv_bfloat16 g_A2[(size_t)B_ * T_ * 2048];       // 128 MB  [hi|mid]
__device__ __nv_bfloat16 g_B2[(size_t)G_ * 2048];            // 2 MB    [hi|mid]

// ---------------------------------------------------------------------------
// fp32 -> 2-way bf16 split: hi = rn(x), mid = rn(x - hi); x ~= hi+mid (2^-17)
// Row layout: [hi(1024) | mid(1024)] bf16, row stride 2048.
// ---------------------------------------------------------------------------
__global__ void convert_split2(const float* __restrict__ X,
                               __nv_bfloat16* __restrict__ OUT, int rows)
{
    size_t i = (size_t)blockIdx.x * blockDim.x + threadIdx.x; // one float4 each
    size_t total = (size_t)rows * (D_ / 4);
    if (i >= total) return;
    float4 v = ((const float4*)X)[i];
    size_t m  = i >> 8;
    int   k4  = (int)(i & 255);

    float xs[4] = {v.x, v.y, v.z, v.w};
    __nv_bfloat16 hi[4], md[4];
#pragma unroll
    for (int c = 0; c < 4; c++) {
        hi[c] = __float2bfloat16(xs[c]);
        float r1 = xs[c] - __bfloat162float(hi[c]);   // exact
        md[c] = __float2bfloat16(r1);
    }

    __nv_bfloat162* dh = (__nv_bfloat162*)(OUT + m * 2048 + k4 * 4);
    __nv_bfloat162* dm = (__nv_bfloat162*)(OUT + m * 2048 + 1024 + k4 * 4);
    dh[0] = __halves2bfloat162(hi[0], hi[1]);
    dh[1] = __halves2bfloat162(hi[2], hi[3]);
    dm[0] = __halves2bfloat162(md[0], md[1]);
    dm[1] = __halves2bfloat162(md[2], md[3]);
}

// ---------------------------------------------------------------------------
// bf16 mma.sync GEMM with explicit cross terms:
//   GX = (Ah+Am)(Bh+Bm)^T + b1 + b2   via 4 phases (h,h)(h,m)(m,h)(m,m),
// each phase a full K=1024 pass; phase selects A/B segment byte offsets.
// M=32768, N=512. CTA tile 128x128, K-tile 64, 8 warps @ 64x32,
// double-buffered cp.async, fragment-major smem (conflict-free ldmatrix).
// ---------------------------------------------------------------------------
__global__ __launch_bounds__(256, 2) void gemm_mma_x(
    const __nv_bfloat16* __restrict__ A2, const __nv_bfloat16* __restrict__ B2,
    const float* __restrict__ b1, const float* __restrict__ b2,
    float* __restrict__ GX)
{
    extern __shared__ char smraw[];
    const uint32_t sbase = smem_u32(smraw);

    const int tid = threadIdx.x;
    const int wid = tid >> 5, lid = tid & 31;
    const int wm  = wid >> 2, wn = wid & 3;     // 2 x 4 warp grid
    const int m0  = blockIdx.y * 128;
    const int n0  = blockIdx.x * 128;

    const char* Ab = (const char*)A2 + (size_t)m0 * 4096;   // row = 2048 bf16
    const char* Bb = (const char*)B2 + (size_t)n0 * 4096;

    float acc[4][4][4];
#pragma unroll
    for (int i = 0; i < 4; i++)
#pragma unroll
        for (int j = 0; j < 4; j++)
#pragma unroll
            for (int r = 0; r < 4; r++) acc[i][j][r] = 0.0f;

    const int mat = lid >> 3, rin = lid & 7;
    const uint32_t aBase = sbase +
        (uint32_t)((((wm * 8 + (mat & 1)) * 8) + (mat >> 1)) * 128 + rin * 16);
    const uint32_t bBase = sbase + 16384 +
        (uint32_t)((((wn * 4 + (mat & 1)) * 8) + (mat >> 1)) * 128 + rin * 16);

    // Phase p: A segment = p>>1 (hi/mid), B segment = p&1 (hi/mid).
    // kt = p*16 + kk; byte offsets within a row:
    //   aoff = (p>>1)*2048 + kk*128,  boff = (p&1)*2048 + kk*128
#define ISSUE(kt, st)                                                          \
    do {                                                                       \
        const int ph_ = (kt) >> 4, kk_ = (kt) & 15;                            \
        const int aoff_ = (ph_ >> 1) * 2048 + kk_ * 128;                       \
        const int boff_ = (ph_ & 1) * 2048 + kk_ * 128;                        \
        uint32_t dA = sbase + (st) * 32768;                                    \
        uint32_t dB = dA + 16384;                                              \
        _Pragma("unroll")                                                      \
        for (int it = 0; it < 4; it++) {                                       \
            int id = tid + it * 256;                                           \
            int kg = id >> 7, mm = id & 127;                                   \
            uint32_t doff = (uint32_t)((((mm >> 3) * 8) + kg) * 128 + (mm & 7) * 16); \
            cp16(dA + doff, Ab + (size_t)mm * 4096 + aoff_ + kg * 16);         \
            cp16(dB + doff, Bb + (size_t)mm * 4096 + boff_ + kg * 16);         \
        }                                                                      \
        asm volatile("cp.async.commit_group;" ::: "memory");                   \
    } while (0)

    ISSUE(0, 0);

    const int NKT = 64;   // 4 phases x 16 k-tiles
    for (int kt = 0; kt < NKT; kt++) {
        const int st = kt & 1;
        if (kt + 1 < NKT) {
            ISSUE(kt + 1, st ^ 1);
            asm volatile("cp.async.wait_group 1;" ::: "memory");
        } else {
            asm volatile("cp.async.wait_group 0;" ::: "memory");
        }
        __syncthreads();

        const uint32_t aS = aBase + st * 32768;
        const uint32_t bS = bBase + st * 32768;
#pragma unroll
        for (int ks = 0; ks < 4; ks++) {
            uint32_t af[4][4], bf[2][4];
#pragma unroll
            for (int i = 0; i < 4; i++)
                ldsm4(af[i], aS + i * 2048 + ks * 256);
#pragma unroll
            for (int jp = 0; jp < 2; jp++)
                ldsm4(bf[jp], bS + jp * 2048 + ks * 256);
#pragma unroll
            for (int i = 0; i < 4; i++)
#pragma unroll
                for (int j = 0; j < 4; j++)
                    mma16816(acc[i][j], af[i],
                             bf[j >> 1][j & 1], bf[j >> 1][2 + (j & 1)]);
        }
        __syncthreads();
    }

    // Epilogue: bias + store fp32
    const int mrow = lid >> 2;
    const int ncol = 2 * (lid & 3);
    float2 bj[4];
#pragma unroll
    for (int j = 0; j < 4; j++) {
        int n = n0 + wn * 32 + j * 8 + ncol;
        bj[j].x = b1[n] + b2[n];
        bj[j].y = b1[n + 1] + b2[n + 1];
    }
#pragma unroll
    for (int i = 0; i < 4; i++) {
        int r0 = m0 + wm * 64 + i * 16 + mrow;
#pragma unroll
        for (int j = 0; j < 4; j++) {
            int n = n0 + wn * 32 + j * 8 + ncol;
            float2 v0 = make_float2(acc[i][j][0] + bj[j].x, acc[i][j][1] + bj[j].y);
            float2 v1 = make_float2(acc[i][j][2] + bj[j].x, acc[i][j][3] + bj[j].y);
            *(float2*)&GX[(size_t)r0 * G_ + n]        = v0;
            *(float2*)&GX[(size_t)(r0 + 8) * G_ + n]  = v1;
        }
    }
}

// ---------------------------------------------------------------------------
// Recurrence v3 (unchanged): 2-CTA cluster per batch, register weights,
// st.async h exchange with mbarrier complete_tx, split own/peer gemv halves.
// ---------------------------------------------------------------------------
__global__ __launch_bounds__(512, 1) __cluster_dims__(2, 1, 1)
void lstm_rec3(const float* __restrict__ GX, const float* __restrict__ Wh,
               float* __restrict__ out, float* __restrict__ hn,
               float* __restrict__ cn)
{
    __shared__ __align__(16) float hbuf[2][128];
    __shared__ __align__(16) float acts[256];
    __shared__ __align__(8) unsigned long long mbar[2];

    const int tid = threadIdx.x;
    uint32_t rank;
    asm("mov.u32 %0, %%cluster_ctarank;" : "=r"(rank));
    const int b    = blockIdx.x >> 1;
    const int rl   = tid >> 1;
    const int p    = tid & 1;
    const int q    = rl >> 6;
    const int j    = rl & 63;
    const int grow = q * 128 + (int)rank * 64 + j;
    const int base = (int)rank * 8;

    u64 wa[16], wb[16];
#pragma unroll
    for (int m = 0; m < 16; m++) {
        int c = p + 2 * ((base + m) & 15);
        float4 w = *(const float4*)&Wh[(size_t)grow * H_ + c * 4];
        wa[m] = pk2(w.x, w.y);
        wb[m] = pk2(w.z, w.w);
    }

    if (tid < 128) { hbuf[0][tid] = 0.0f; hbuf[1][tid] = 0.0f; }
    uint32_t mb_loc0 = smem_u32(&mbar[0]);
    uint32_t mb_loc1 = smem_u32(&mbar[1]);
    if (tid == 0) {
        asm volatile("mbarrier.init.shared.b64 [%0], 1;" :: "r"(mb_loc0) : "memory");
        asm volatile("mbarrier.init.shared.b64 [%0], 1;" :: "r"(mb_loc1) : "memory");
        asm volatile("mbarrier.arrive.expect_tx.shared.b64 _, [%0], 256;" :: "r"(mb_loc0) : "memory");
        asm volatile("mbarrier.arrive.expect_tx.shared.b64 _, [%0], 256;" :: "r"(mb_loc1) : "memory");
    }

    uint32_t ph_peer0, ph_peer1, pm_peer0, pm_peer1;
    {
        const uint32_t r_ = rank ^ 1u;
        int hid = (int)rank * 64 + (tid & 63);
        uint32_t l0 = smem_u32(&hbuf[0][hid]);
        uint32_t l1 = smem_u32(&hbuf[1][hid]);
        asm("mapa.shared::cluster.u32 %0, %1, %2;" : "=r"(ph_peer0) : "r"(l0), "r"(r_));
        asm("mapa.shared::cluster.u32 %0, %1, %2;" : "=r"(ph_peer1) : "r"(l1), "r"(r_));
        asm("mapa.shared::cluster.u32 %0, %1, %2;" : "=r"(pm_peer0) : "r"(mb_loc0), "r"(r_));
        asm("mapa.shared::cluster.u32 %0, %1, %2;" : "=r"(pm_peer1) : "r"(mb_loc1), "r"(r_));
    }

    const float* gxb = GX + (size_t)b * T_ * G_;
    float* outb      = out + (size_t)b * T_ * H_;
    float gxv = (p == 0) ? __ldg(&gxb[grow]) : 0.0f;
    float cst = 0.0f;
    int ph0 = 0, ph1 = 0;

    asm volatile("barrier.cluster.arrive.aligned;" ::: "memory");
    asm volatile("barrier.cluster.wait.aligned;" ::: "memory");

    for (int t = 0; t < T_; t++) {
        const int cb = t & 1, nb = cb ^ 1;
        const ulonglong2* h2 = (const ulonglong2*)hbuf[cb];

        u64 acc0 = pk2(0.0f, 0.0f), acc1 = pk2(0.0f, 0.0f);
#pragma unroll
        for (int m = 0; m < 8; m++) {
            ulonglong2 hh = h2[p + 2 * ((base + m) & 15)];
            fma2(acc0, hh.x, wa[m]);
            fma2(acc1, hh.y, wb[m]);
        }
        if (t > 0) {
            uint32_t mb = cb ? mb_loc1 : mb_loc0;
            int par = cb ? ph1 : ph0;
            asm volatile(
                "{\n\t.reg .pred P;\n\t"
                "WL%=:\n\t"
                "mbarrier.try_wait.parity.acquire.cluster.shared::cta.b64 P, [%0], %1, 0x989680;\n\t"
                "@P bra WD%=;\n\t"
                "bra WL%=;\n\t"
                "WD%=:\n\t}"
                :: "r"(mb), "r"(par) : "memory");
            if (cb) ph1 ^= 1; else ph0 ^= 1;
            if (tid == 0)
                asm volatile("mbarrier.arrive.expect_tx.shared.b64 _, [%0], 256;"
                             :: "r"(mb) : "memory");
        }
#pragma unroll
        for (int m = 8; m < 16; m++) {
            ulonglong2 hh = h2[p + 2 * ((base + m) & 15)];
            fma2(acc0, hh.x, wa[m]);
            fma2(acc1, hh.y, wb[m]);
        }
        float2 u0 = upk2(acc0), u1 = upk2(acc1);
        float s = (u0.x + u0.y) + (u1.x + u1.y);
        s += __shfl_xor_sync(0xffffffffu, s, 1);

        if (p == 0) {
            float g = s + gxv;
            acts[rl] = (q == 2) ? fast_tanh(g) : fast_sigmoid(g);
            if (t + 1 < T_) gxv = __ldg(&gxb[(size_t)(t + 1) * G_ + grow]);
        }
        __syncthreads();

        if (tid < 64) {
            float ig = acts[tid];
            float fg = acts[64 + tid];
            float gg = acts[128 + tid];
            float og = acts[192 + tid];
            cst = fg * cst + ig * gg;
            float hv = og * fast_tanh(cst);
            const int hid = (int)rank * 64 + tid;
            hbuf[nb][hid] = hv;
            {
                uint32_t pa = nb ? ph_peer1 : ph_peer0;
                uint32_t pm = nb ? pm_peer1 : pm_peer0;
                asm volatile(
                    "st.async.shared::cluster.mbarrier::complete_tx::bytes.b32 [%0], %1, [%2];"
                    :: "r"(pa), "r"(__float_as_uint(hv)), "r"(pm) : "memory");
            }
            outb[(size_t)t * H_ + hid] = hv;
            if (t == T_ - 1) {
                hn[b * H_ + hid] = hv;
                cn[b * H_ + hid] = cst;
            }
        }
        __syncthreads();
    }
}

// ---------------------------------------------------------------------------
extern "C" void kernel_launch(void* const* d_in, const int* in_sizes, int n_in,
                              void* d_out, int out_size)
{
    const float* x   = (const float*)d_in[0];
    const float* Wih = (const float*)d_in[1];
    const float* Whh = (const float*)d_in[2];
    const float* bih = (const float*)d_in[3];
    const float* bhh = (const float*)d_in[4];
    float* out = (float*)d_out;

    float* gx = nullptr;
    cudaGetSymbolAddress((void**)&gx, g_gx);
    __nv_bfloat16* A2 = nullptr;
    cudaGetSymbolAddress((void**)&A2, g_A2);
    __nv_bfloat16* B2 = nullptr;
    cudaGetSymbolAddress((void**)&B2, g_B2);

    convert_split2<<<(B_ * T_ * (D_ / 4) + 255) / 256, 256>>>(x, A2, B_ * T_);
    convert_split2<<<(G_ * (D_ / 4) + 255) / 256, 256>>>(Wih, B2, G_);

    cudaFuncSetAttribute(gemm_mma_x, cudaFuncAttributeMaxDynamicSharedMemorySize, 65536);
    dim3 grid(4, 256);
    gemm_mma_x<<<grid, 256, 65536>>>(A2, B2, bih, bhh, gx);

    float* hn = out + (size_t)B_ * T_ * H_;
    float* cn = hn + (size_t)B_ * H_;
    lstm_rec3<<<B_ * 2, 512>>>(gx, Whh, out, hn, cn);
}

// round 8
// speedup vs baseline: 1.7560x; 1.1568x over previous
#include <cuda_runtime.h>
#include <cuda_bf16.h>
#include <cstdint>

// LSTM: B=32, T=1024, D=1024, H=128  (gates 4H=512, order i,f,g,o)
// out layout: [B*T*H floats][h_n: B*H][c_n: B*H]

#define B_ 32
#define T_ 1024
#define D_ 1024
#define H_ 128
#define G_ 512

typedef unsigned long long u64;

__device__ __forceinline__ u64 pk2(float x, float y) {
    u64 r;
    asm("mov.b64 %0, {%1, %2};" : "=l"(r)
        : "r"(__float_as_uint(x)), "r"(__float_as_uint(y)));
    return r;
}
__device__ __forceinline__ float2 upk2(u64 v) {
    unsigned lo, hi;
    asm("mov.b64 {%0, %1}, %2;" : "=r"(lo), "=r"(hi) : "l"(v));
    return make_float2(__uint_as_float(lo), __uint_as_float(hi));
}
__device__ __forceinline__ void fma2(u64 &c, u64 a, u64 b) {
    asm("fma.rn.f32x2 %0, %1, %2, %0;" : "+l"(c) : "l"(a), "l"(b));
}
__device__ __forceinline__ float fast_sigmoid(float x) {
    return 1.0f / (1.0f + __expf(-x));
}
__device__ __forceinline__ float fast_tanh(float x) {
    return 1.0f - 2.0f / (__expf(2.0f * x) + 1.0f);
}
__device__ __forceinline__ uint32_t smem_u32(const void* p) {
    uint32_t a;
    asm("{ .reg .u64 t; cvta.to.shared.u64 t, %1; cvt.u32.u64 %0, t; }"
        : "=r"(a) : "l"(p));
    return a;
}
__device__ __forceinline__ void cp16(uint32_t dst, const void* src) {
    asm volatile("cp.async.cg.shared.global [%0], [%1], 16;"
                 :: "r"(dst), "l"(src));
}
__device__ __forceinline__ void ldsm4(uint32_t* r, uint32_t addr) {
    asm volatile("ldmatrix.sync.aligned.m8n8.x4.shared.b16 {%0,%1,%2,%3}, [%4];"
                 : "=r"(r[0]), "=r"(r[1]), "=r"(r[2]), "=r"(r[3]) : "r"(addr));
}
__device__ __forceinline__ void mma16816(float* d, const uint32_t* a,
                                         uint32_t b0, uint32_t b1) {
    asm volatile(
        "mma.sync.aligned.m16n8k16.row.col.f32.bf16.bf16.f32 "
        "{%0,%1,%2,%3}, {%4,%5,%6,%7}, {%8,%9}, {%0,%1,%2,%3};"
        : "+f"(d[0]), "+f"(d[1]), "+f"(d[2]), "+f"(d[3])
        : "r"(a[0]), "r"(a[1]), "r"(a[2]), "r"(a[3]), "r"(b0), "r"(b1));
}

// Scratch (__device__ globals: allocation-free)
__device__ float g_gx[(size_t)B_ * T_ * G_];                 // 64 MB
__device__ __nv_bfloat16 g_A2[(size_t)B_ * T_ * 2048];       // 128 MB  [hi|mid]
__device__ __nv_bfloat16 g_B2[(size_t)G_ * 2048];            // 2 MB    [hi|mid]

// ---------------------------------------------------------------------------
// fp32 -> 2-way bf16 split: hi = rn(x), mid = rn(x - hi); x ~= hi+mid (2^-17)
// Row layout: [hi(1024) | mid(1024)] bf16, row stride 2048.
// ---------------------------------------------------------------------------
__global__ void convert_split2(const float* __restrict__ X,
                               __nv_bfloat16* __restrict__ OUT, int rows)
{
    size_t i = (size_t)blockIdx.x * blockDim.x + threadIdx.x; // one float4 each
    size_t total = (size_t)rows * (D_ / 4);
    if (i >= total) return;
    float4 v = ((const float4*)X)[i];
    size_t m  = i >> 8;
    int   k4  = (int)(i & 255);

    float xs[4] = {v.x, v.y, v.z, v.w};
    __nv_bfloat16 hi[4], md[4];
#pragma unroll
    for (int c = 0; c < 4; c++) {
        hi[c] = __float2bfloat16(xs[c]);
        float r1 = xs[c] - __bfloat162float(hi[c]);   // exact
        md[c] = __float2bfloat16(r1);
    }

    __nv_bfloat162* dh = (__nv_bfloat162*)(OUT + m * 2048 + k4 * 4);
    __nv_bfloat162* dm = (__nv_bfloat162*)(OUT + m * 2048 + 1024 + k4 * 4);
    dh[0] = __halves2bfloat162(hi[0], hi[1]);
    dh[1] = __halves2bfloat162(hi[2], hi[3]);
    dm[0] = __halves2bfloat162(md[0], md[1]);
    dm[1] = __halves2bfloat162(md[2], md[3]);
}

// ---------------------------------------------------------------------------
// bf16 mma.sync GEMM with explicit cross terms, 3 phases:
//   GX ~= Ah.Bh + Ah.Bm + Am.Bh  (+b1+b2);  dropped Am.Bm ~ 2^-16.
// M=32768, N=512, K=1024/phase. CTA tile 128x128, K-tile 64, 8 warps @ 64x32,
// double-buffered COALESCED cp.async (8 lanes share one 128B line),
// fragment-major smem (conflict-free ldmatrix).
// ---------------------------------------------------------------------------
__global__ __launch_bounds__(256, 2) void gemm_mma_x(
    const __nv_bfloat16* __restrict__ A2, const __nv_bfloat16* __restrict__ B2,
    const float* __restrict__ b1, const float* __restrict__ b2,
    float* __restrict__ GX)
{
    extern __shared__ char smraw[];
    const uint32_t sbase = smem_u32(smraw);

    const int tid = threadIdx.x;
    const int wid = tid >> 5, lid = tid & 31;
    const int wm  = wid >> 2, wn = wid & 3;     // 2 x 4 warp grid
    const int m0  = blockIdx.y * 128;
    const int n0  = blockIdx.x * 128;

    const char* Ab = (const char*)A2 + (size_t)m0 * 4096;   // row = 2048 bf16
    const char* Bb = (const char*)B2 + (size_t)n0 * 4096;

    float acc[4][4][4];
#pragma unroll
    for (int i = 0; i < 4; i++)
#pragma unroll
        for (int j = 0; j < 4; j++)
#pragma unroll
            for (int r = 0; r < 4; r++) acc[i][j][r] = 0.0f;

    const int mat = lid >> 3, rin = lid & 7;
    const uint32_t aBase = sbase +
        (uint32_t)((((wm * 8 + (mat & 1)) * 8) + (mat >> 1)) * 128 + rin * 16);
    const uint32_t bBase = sbase + 16384 +
        (uint32_t)((((wn * 4 + (mat & 1)) * 8) + (mat >> 1)) * 128 + rin * 16);

    // Phase p (kt>>4): 0=(h,h) 1=(h,m) 2=(m,h).  kk = kt & 15.
    // Granule id: mm = id>>3 (row), kg = id&7 (16B col) -> 8 lanes = one 128B line.
#define ISSUE(kt, st)                                                          \
    do {                                                                       \
        const int ph_ = (kt) >> 4, kk_ = (kt) & 15;                            \
        const int aoff_ = ((ph_ == 2) ? 2048 : 0) + kk_ * 128;                 \
        const int boff_ = ((ph_ == 1) ? 2048 : 0) + kk_ * 128;                 \
        uint32_t dA = sbase + (st) * 32768;                                    \
        uint32_t dB = dA + 16384;                                              \
        _Pragma("unroll")                                                      \
        for (int it = 0; it < 4; it++) {                                       \
            int id = tid + it * 256;                                           \
            int mm = id >> 3, kg = id & 7;                                     \
            uint32_t doff = (uint32_t)((((mm >> 3) * 8) + kg) * 128 + (mm & 7) * 16); \
            cp16(dA + doff, Ab + (size_t)mm * 4096 + aoff_ + kg * 16);         \
            cp16(dB + doff, Bb + (size_t)mm * 4096 + boff_ + kg * 16);         \
        }                                                                      \
        asm volatile("cp.async.commit_group;" ::: "memory");                   \
    } while (0)

    ISSUE(0, 0);

    const int NKT = 48;   // 3 phases x 16 k-tiles
    for (int kt = 0; kt < NKT; kt++) {
        const int st = kt & 1;
        if (kt + 1 < NKT) {
            ISSUE(kt + 1, st ^ 1);
            asm volatile("cp.async.wait_group 1;" ::: "memory");
        } else {
            asm volatile("cp.async.wait_group 0;" ::: "memory");
        }
        __syncthreads();

        const uint32_t aS = aBase + st * 32768;
        const uint32_t bS = bBase + st * 32768;
#pragma unroll
        for (int ks = 0; ks < 4; ks++) {
            uint32_t af[4][4], bf[2][4];
#pragma unroll
            for (int i = 0; i < 4; i++)
                ldsm4(af[i], aS + i * 2048 + ks * 256);
#pragma unroll
            for (int jp = 0; jp < 2; jp++)
                ldsm4(bf[jp], bS + jp * 2048 + ks * 256);
#pragma unroll
            for (int i = 0; i < 4; i++)
#pragma unroll
                for (int j = 0; j < 4; j++)
                    mma16816(acc[i][j], af[i],
                             bf[j >> 1][j & 1], bf[j >> 1][2 + (j & 1)]);
        }
        __syncthreads();
    }

    // Epilogue: bias + store fp32
    const int mrow = lid >> 2;
    const int ncol = 2 * (lid & 3);
    float2 bj[4];
#pragma unroll
    for (int j = 0; j < 4; j++) {
        int n = n0 + wn * 32 + j * 8 + ncol;
        bj[j].x = b1[n] + b2[n];
        bj[j].y = b1[n + 1] + b2[n + 1];
    }
#pragma unroll
    for (int i = 0; i < 4; i++) {
        int r0 = m0 + wm * 64 + i * 16 + mrow;
#pragma unroll
        for (int j = 0; j < 4; j++) {
            int n = n0 + wn * 32 + j * 8 + ncol;
            float2 v0 = make_float2(acc[i][j][0] + bj[j].x, acc[i][j][1] + bj[j].y);
            float2 v1 = make_float2(acc[i][j][2] + bj[j].x, acc[i][j][3] + bj[j].y);
            *(float2*)&GX[(size_t)r0 * G_ + n]        = v0;
            *(float2*)&GX[(size_t)(r0 + 8) * G_ + n]  = v1;
        }
    }
}

// ---------------------------------------------------------------------------
// Recurrence v3 (unchanged): 2-CTA cluster per batch, register weights,
// st.async h exchange with mbarrier complete_tx, split own/peer gemv halves.
// ---------------------------------------------------------------------------
__global__ __launch_bounds__(512, 1) __cluster_dims__(2, 1, 1)
void lstm_rec3(const float* __restrict__ GX, const float* __restrict__ Wh,
               float* __restrict__ out, float* __restrict__ hn,
               float* __restrict__ cn)
{
    __shared__ __align__(16) float hbuf[2][128];
    __shared__ __align__(16) float acts[256];
    __shared__ __align__(8) unsigned long long mbar[2];

    const int tid = threadIdx.x;
    uint32_t rank;
    asm("mov.u32 %0, %%cluster_ctarank;" : "=r"(rank));
    const int b    = blockIdx.x >> 1;
    const int rl   = tid >> 1;
    const int p    = tid & 1;
    const int q    = rl >> 6;
    const int j    = rl & 63;
    const int grow = q * 128 + (int)rank * 64 + j;
    const int base = (int)rank * 8;

    u64 wa[16], wb[16];
#pragma unroll
    for (int m = 0; m < 16; m++) {
        int c = p + 2 * ((base + m) & 15);
        float4 w = *(const float4*)&Wh[(size_t)grow * H_ + c * 4];
        wa[m] = pk2(w.x, w.y);
        wb[m] = pk2(w.z, w.w);
    }

    if (tid < 128) { hbuf[0][tid] = 0.0f; hbuf[1][tid] = 0.0f; }
    uint32_t mb_loc0 = smem_u32(&mbar[0]);
    uint32_t mb_loc1 = smem_u32(&mbar[1]);
    if (tid == 0) {
        asm volatile("mbarrier.init.shared.b64 [%0], 1;" :: "r"(mb_loc0) : "memory");
        asm volatile("mbarrier.init.shared.b64 [%0], 1;" :: "r"(mb_loc1) : "memory");
        asm volatile("mbarrier.arrive.expect_tx.shared.b64 _, [%0], 256;" :: "r"(mb_loc0) : "memory");
        asm volatile("mbarrier.arrive.expect_tx.shared.b64 _, [%0], 256;" :: "r"(mb_loc1) : "memory");
    }

    uint32_t ph_peer0, ph_peer1, pm_peer0, pm_peer1;
    {
        const uint32_t r_ = rank ^ 1u;
        int hid = (int)rank * 64 + (tid & 63);
        uint32_t l0 = smem_u32(&hbuf[0][hid]);
        uint32_t l1 = smem_u32(&hbuf[1][hid]);
        asm("mapa.shared::cluster.u32 %0, %1, %2;" : "=r"(ph_peer0) : "r"(l0), "r"(r_));
        asm("mapa.shared::cluster.u32 %0, %1, %2;" : "=r"(ph_peer1) : "r"(l1), "r"(r_));
        asm("mapa.shared::cluster.u32 %0, %1, %2;" : "=r"(pm_peer0) : "r"(mb_loc0), "r"(r_));
        asm("mapa.shared::cluster.u32 %0, %1, %2;" : "=r"(pm_peer1) : "r"(mb_loc1), "r"(r_));
    }

    const float* gxb = GX + (size_t)b * T_ * G_;
    float* outb      = out + (size_t)b * T_ * H_;
    float gxv = (p == 0) ? __ldg(&gxb[grow]) : 0.0f;
    float cst = 0.0f;
    int ph0 = 0, ph1 = 0;

    asm volatile("barrier.cluster.arrive.aligned;" ::: "memory");
    asm volatile("barrier.cluster.wait.aligned;" ::: "memory");

    for (int t = 0; t < T_; t++) {
        const int cb = t & 1, nb = cb ^ 1;
        const ulonglong2* h2 = (const ulonglong2*)hbuf[cb];

        u64 acc0 = pk2(0.0f, 0.0f), acc1 = pk2(0.0f, 0.0f);
#pragma unroll
        for (int m = 0; m < 8; m++) {
            ulonglong2 hh = h2[p + 2 * ((base + m) & 15)];
            fma2(acc0, hh.x, wa[m]);
            fma2(acc1, hh.y, wb[m]);
        }
        if (t > 0) {
            uint32_t mb = cb ? mb_loc1 : mb_loc0;
            int par = cb ? ph1 : ph0;
            asm volatile(
                "{\n\t.reg .pred P;\n\t"
                "WL%=:\n\t"
                "mbarrier.try_wait.parity.acquire.cluster.shared::cta.b64 P, [%0], %1, 0x989680;\n\t"
                "@P bra WD%=;\n\t"
                "bra WL%=;\n\t"
                "WD%=:\n\t}"
                :: "r"(mb), "r"(par) : "memory");
            if (cb) ph1 ^= 1; else ph0 ^= 1;
            if (tid == 0)
                asm volatile("mbarrier.arrive.expect_tx.shared.b64 _, [%0], 256;"
                             :: "r"(mb) : "memory");
        }
#pragma unroll
        for (int m = 8; m < 16; m++) {
            ulonglong2 hh = h2[p + 2 * ((base + m) & 15)];
            fma2(acc0, hh.x, wa[m]);
            fma2(acc1, hh.y, wb[m]);
        }
        float2 u0 = upk2(acc0), u1 = upk2(acc1);
        float s = (u0.x + u0.y) + (u1.x + u1.y);
        s += __shfl_xor_sync(0xffffffffu, s, 1);

        if (p == 0) {
            float g = s + gxv;
            acts[rl] = (q == 2) ? fast_tanh(g) : fast_sigmoid(g);
            if (t + 1 < T_) gxv = __ldg(&gxb[(size_t)(t + 1) * G_ + grow]);
        }
        __syncthreads();

        if (tid < 64) {
            float ig = acts[tid];
            float fg = acts[64 + tid];
            float gg = acts[128 + tid];
            float og = acts[192 + tid];
            cst = fg * cst + ig * gg;
            float hv = og * fast_tanh(cst);
            const int hid = (int)rank * 64 + tid;
            hbuf[nb][hid] = hv;
            {
                uint32_t pa = nb ? ph_peer1 : ph_peer0;
                uint32_t pm = nb ? pm_peer1 : pm_peer0;
                asm volatile(
                    "st.async.shared::cluster.mbarrier::complete_tx::bytes.b32 [%0], %1, [%2];"
                    :: "r"(pa), "r"(__float_as_uint(hv)), "r"(pm) : "memory");
            }
            outb[(size_t)t * H_ + hid] = hv;
            if (t == T_ - 1) {
                hn[b * H_ + hid] = hv;
                cn[b * H_ + hid] = cst;
            }
        }
        __syncthreads();
    }
}

// ---------------------------------------------------------------------------
extern "C" void kernel_launch(void* const* d_in, const int* in_sizes, int n_in,
                              void* d_out, int out_size)
{
    const float* x   = (const float*)d_in[0];
    const float* Wih = (const float*)d_in[1];
    const float* Whh = (const float*)d_in[2];
    const float* bih = (const float*)d_in[3];
    const float* bhh = (const float*)d_in[4];
    float* out = (float*)d_out;

    float* gx = nullptr;
    cudaGetSymbolAddress((void**)&gx, g_gx);
    __nv_bfloat16* A2 = nullptr;
    cudaGetSymbolAddress((void**)&A2, g_A2);
    __nv_bfloat16* B2 = nullptr;
    cudaGetSymbolAddress((void**)&B2, g_B2);

    convert_split2<<<(B_ * T_ * (D_ / 4) + 255) / 256, 256>>>(x, A2, B_ * T_);
    convert_split2<<<(G_ * (D_ / 4) + 255) / 256, 256>>>(Wih, B2, G_);

    cudaFuncSetAttribute(gemm_mma_x, cudaFuncAttributeMaxDynamicSharedMemorySize, 65536);
    dim3 grid(4, 256);
    gemm_mma_x<<<grid, 256, 65536>>>(A2, B2, bih, bhh, gx);

    float* hn = out + (size_t)B_ * T_ * H_;
    float* cn = hn + (size_t)B_ * H_;
    lstm_rec3<<<B_ * 2, 512>>>(gx, Whh, out, hn, cn);
}

// round 9
// speedup vs baseline: 1.7574x; 1.0008x over previous
#include <cuda_runtime.h>
#include <cuda_bf16.h>
#include <cstdint>

// LSTM: B=32, T=1024, D=1024, H=128  (gates 4H=512, order i,f,g,o)
// out layout: [B*T*H floats][h_n: B*H][c_n: B*H]

#define B_ 32
#define T_ 1024
#define D_ 1024
#define H_ 128
#define G_ 512

typedef unsigned long long u64;

__device__ __forceinline__ u64 pk2(float x, float y) {
    u64 r;
    asm("mov.b64 %0, {%1, %2};" : "=l"(r)
        : "r"(__float_as_uint(x)), "r"(__float_as_uint(y)));
    return r;
}
__device__ __forceinline__ float2 upk2(u64 v) {
    unsigned lo, hi;
    asm("mov.b64 {%0, %1}, %2;" : "=r"(lo), "=r"(hi) : "l"(v));
    return make_float2(__uint_as_float(lo), __uint_as_float(hi));
}
__device__ __forceinline__ void fma2(u64 &c, u64 a, u64 b) {
    asm("fma.rn.f32x2 %0, %1, %2, %0;" : "+l"(c) : "l"(a), "l"(b));
}
__device__ __forceinline__ float fast_sigmoid(float x) {
    return 1.0f / (1.0f + __expf(-x));
}
__device__ __forceinline__ float fast_tanh(float x) {
    return 1.0f - 2.0f / (__expf(2.0f * x) + 1.0f);
}
__device__ __forceinline__ uint32_t smem_u32(const void* p) {
    uint32_t a;
    asm("{ .reg .u64 t; cvta.to.shared.u64 t, %1; cvt.u32.u64 %0, t; }"
        : "=r"(a) : "l"(p));
    return a;
}
__device__ __forceinline__ void cp16(uint32_t dst, const void* src) {
    asm volatile("cp.async.cg.shared.global [%0], [%1], 16;"
                 :: "r"(dst), "l"(src));
}
__device__ __forceinline__ void ldsm4(uint32_t* r, uint32_t addr) {
    asm volatile("ldmatrix.sync.aligned.m8n8.x4.shared.b16 {%0,%1,%2,%3}, [%4];"
                 : "=r"(r[0]), "=r"(r[1]), "=r"(r[2]), "=r"(r[3]) : "r"(addr));
}
__device__ __forceinline__ void mma16816(float* d, const uint32_t* a,
                                         uint32_t b0, uint32_t b1) {
    asm volatile(
        "mma.sync.aligned.m16n8k16.row.col.f32.bf16.bf16.f32 "
        "{%0,%1,%2,%3}, {%4,%5,%6,%7}, {%8,%9}, {%0,%1,%2,%3};"
        : "+f"(d[0]), "+f"(d[1]), "+f"(d[2]), "+f"(d[3])
        : "r"(a[0]), "r"(a[1]), "r"(a[2]), "r"(a[3]), "r"(b0), "r"(b1));
}

// Scratch (__device__ globals: allocation-free)
__device__ float g_gx[(size_t)B_ * T_ * G_];                 // 64 MB
__device__ __nv_bfloat16 g_A2[(size_t)B_ * T_ * 2048];       // 128 MB  [hi|mid]
__device__ __nv_bfloat16 g_B2[(size_t)G_ * 2048];            // 2 MB    [hi|mid]
__device__ int g_flag[256];   // per m-tile completion counters (target 4)

__global__ void reset_flags() { g_flag[threadIdx.x] = 0; }

// ---------------------------------------------------------------------------
// fp32 -> 2-way bf16 split: hi = rn(x), mid = rn(x - hi); x ~= hi+mid (2^-17)
// ---------------------------------------------------------------------------
__global__ void convert_split2(const float* __restrict__ X,
                               __nv_bfloat16* __restrict__ OUT, int rows)
{
    size_t i = (size_t)blockIdx.x * blockDim.x + threadIdx.x;
    size_t total = (size_t)rows * (D_ / 4);
    if (i >= total) return;
    float4 v = ((const float4*)X)[i];
    size_t m  = i >> 8;
    int   k4  = (int)(i & 255);

    float xs[4] = {v.x, v.y, v.z, v.w};
    __nv_bfloat16 hi[4], md[4];
#pragma unroll
    for (int c = 0; c < 4; c++) {
        hi[c] = __float2bfloat16(xs[c]);
        float r1 = xs[c] - __bfloat162float(hi[c]);
        md[c] = __float2bfloat16(r1);
    }

    __nv_bfloat162* dh = (__nv_bfloat162*)(OUT + m * 2048 + k4 * 4);
    __nv_bfloat162* dm = (__nv_bfloat162*)(OUT + m * 2048 + 1024 + k4 * 4);
    dh[0] = __halves2bfloat162(hi[0], hi[1]);
    dh[1] = __halves2bfloat162(hi[2], hi[3]);
    dm[0] = __halves2bfloat162(md[0], md[1]);
    dm[1] = __halves2bfloat162(md[2], md[3]);
}

// ---------------------------------------------------------------------------
// bf16 mma.sync GEMM, 3 phases (h,h)(h,m)(m,h). m-tiles ordered tc-major so
// early timestep chunks of ALL batches are produced first; each m-tile's 4
// n-CTAs bump g_flag[y] on completion (producer side of the overlap).
// ---------------------------------------------------------------------------
__global__ __launch_bounds__(256, 2) void gemm_mma_x(
    const __nv_bfloat16* __restrict__ A2, const __nv_bfloat16* __restrict__ B2,
    const float* __restrict__ b1, const float* __restrict__ b2,
    float* __restrict__ GX)
{
    extern __shared__ char smraw[];
    const uint32_t sbase = smem_u32(smraw);

    const int tid = threadIdx.x;
    const int wid = tid >> 5, lid = tid & 31;
    const int wm  = wid >> 2, wn = wid & 3;
    const int y   = blockIdx.y;            // 256 m-tiles, tc-major
    const int bb  = y & 31, tc = y >> 5;
    const int m0  = bb * 1024 + tc * 128;
    const int n0  = blockIdx.x * 128;

    const char* Ab = (const char*)A2 + (size_t)m0 * 4096;
    const char* Bb = (const char*)B2 + (size_t)n0 * 4096;

    float acc[4][4][4];
#pragma unroll
    for (int i = 0; i < 4; i++)
#pragma unroll
        for (int j = 0; j < 4; j++)
#pragma unroll
            for (int r = 0; r < 4; r++) acc[i][j][r] = 0.0f;

    const int mat = lid >> 3, rin = lid & 7;
    const uint32_t aBase = sbase +
        (uint32_t)((((wm * 8 + (mat & 1)) * 8) + (mat >> 1)) * 128 + rin * 16);
    const uint32_t bBase = sbase + 16384 +
        (uint32_t)((((wn * 4 + (mat & 1)) * 8) + (mat >> 1)) * 128 + rin * 16);

#define ISSUE(kt, st)                                                          \
    do {                                                                       \
        const int ph_ = (kt) >> 4, kk_ = (kt) & 15;                            \
        const int aoff_ = ((ph_ == 2) ? 2048 : 0) + kk_ * 128;                 \
        const int boff_ = ((ph_ == 1) ? 2048 : 0) + kk_ * 128;                 \
        uint32_t dA = sbase + (st) * 32768;                                    \
        uint32_t dB = dA + 16384;                                              \
        _Pragma("unroll")                                                      \
        for (int it = 0; it < 4; it++) {                                       \
            int id = tid + it * 256;                                           \
            int mm = id >> 3, kg = id & 7;                                     \
            uint32_t doff = (uint32_t)((((mm >> 3) * 8) + kg) * 128 + (mm & 7) * 16); \
            cp16(dA + doff, Ab + (size_t)mm * 4096 + aoff_ + kg * 16);         \
            cp16(dB + doff, Bb + (size_t)mm * 4096 + boff_ + kg * 16);         \
        }                                                                      \
        asm volatile("cp.async.commit_group;" ::: "memory");                   \
    } while (0)

    ISSUE(0, 0);

    const int NKT = 48;
    for (int kt = 0; kt < NKT; kt++) {
        const int st = kt & 1;
        if (kt + 1 < NKT) {
            ISSUE(kt + 1, st ^ 1);
            asm volatile("cp.async.wait_group 1;" ::: "memory");
        } else {
            asm volatile("cp.async.wait_group 0;" ::: "memory");
        }
        __syncthreads();

        const uint32_t aS = aBase + st * 32768;
        const uint32_t bS = bBase + st * 32768;
#pragma unroll
        for (int ks = 0; ks < 4; ks++) {
            uint32_t af[4][4], bf[2][4];
#pragma unroll
            for (int i = 0; i < 4; i++)
                ldsm4(af[i], aS + i * 2048 + ks * 256);
#pragma unroll
            for (int jp = 0; jp < 2; jp++)
                ldsm4(bf[jp], bS + jp * 2048 + ks * 256);
#pragma unroll
            for (int i = 0; i < 4; i++)
#pragma unroll
                for (int j = 0; j < 4; j++)
                    mma16816(acc[i][j], af[i],
                             bf[j >> 1][j & 1], bf[j >> 1][2 + (j & 1)]);
        }
        __syncthreads();
    }

    // Epilogue: bias + store fp32, then signal tile completion
    const int mrow = lid >> 2;
    const int ncol = 2 * (lid & 3);
    float2 bj[4];
#pragma unroll
    for (int j = 0; j < 4; j++) {
        int n = n0 + wn * 32 + j * 8 + ncol;
        bj[j].x = b1[n] + b2[n];
        bj[j].y = b1[n + 1] + b2[n + 1];
    }
#pragma unroll
    for (int i = 0; i < 4; i++) {
        int r0 = m0 + wm * 64 + i * 16 + mrow;
#pragma unroll
        for (int j = 0; j < 4; j++) {
            int n = n0 + wn * 32 + j * 8 + ncol;
            float2 v0 = make_float2(acc[i][j][0] + bj[j].x, acc[i][j][1] + bj[j].y);
            float2 v1 = make_float2(acc[i][j][2] + bj[j].x, acc[i][j][3] + bj[j].y);
            *(float2*)&GX[(size_t)r0 * G_ + n]        = v0;
            *(float2*)&GX[(size_t)(r0 + 8) * G_ + n]  = v1;
        }
    }
    __threadfence();
    __syncthreads();
    if (tid == 0) atomicAdd(&g_flag[y], 1);
}

// ---------------------------------------------------------------------------
// Recurrence v4: identical to v3 plus per-128-step tile gating on g_flag
// (consumer side of the overlap) and boundary-safe gx prefetch.
// ---------------------------------------------------------------------------
__global__ __launch_bounds__(512, 1) __cluster_dims__(2, 1, 1)
void lstm_rec4(const float* __restrict__ GX, const float* __restrict__ Wh,
               float* __restrict__ out, float* __restrict__ hn,
               float* __restrict__ cn)
{
    __shared__ __align__(16) float hbuf[2][128];
    __shared__ __align__(16) float acts[256];
    __shared__ __align__(8) unsigned long long mbar[2];

    const int tid = threadIdx.x;
    uint32_t rank;
    asm("mov.u32 %0, %%cluster_ctarank;" : "=r"(rank));
    const int b    = blockIdx.x >> 1;
    const int rl   = tid >> 1;
    const int p    = tid & 1;
    const int q    = rl >> 6;
    const int j    = rl & 63;
    const int grow = q * 128 + (int)rank * 64 + j;
    const int base = (int)rank * 8;

    u64 wa[16], wb[16];
#pragma unroll
    for (int m = 0; m < 16; m++) {
        int c = p + 2 * ((base + m) & 15);
        float4 w = *(const float4*)&Wh[(size_t)grow * H_ + c * 4];
        wa[m] = pk2(w.x, w.y);
        wb[m] = pk2(w.z, w.w);
    }

    if (tid < 128) { hbuf[0][tid] = 0.0f; hbuf[1][tid] = 0.0f; }
    uint32_t mb_loc0 = smem_u32(&mbar[0]);
    uint32_t mb_loc1 = smem_u32(&mbar[1]);
    if (tid == 0) {
        asm volatile("mbarrier.init.shared.b64 [%0], 1;" :: "r"(mb_loc0) : "memory");
        asm volatile("mbarrier.init.shared.b64 [%0], 1;" :: "r"(mb_loc1) : "memory");
        asm volatile("mbarrier.arrive.expect_tx.shared.b64 _, [%0], 256;" :: "r"(mb_loc0) : "memory");
        asm volatile("mbarrier.arrive.expect_tx.shared.b64 _, [%0], 256;" :: "r"(mb_loc1) : "memory");
    }

    uint32_t ph_peer0, ph_peer1, pm_peer0, pm_peer1;
    {
        const uint32_t r_ = rank ^ 1u;
        int hid = (int)rank * 64 + (tid & 63);
        uint32_t l0 = smem_u32(&hbuf[0][hid]);
        uint32_t l1 = smem_u32(&hbuf[1][hid]);
        asm("mapa.shared::cluster.u32 %0, %1, %2;" : "=r"(ph_peer0) : "r"(l0), "r"(r_));
        asm("mapa.shared::cluster.u32 %0, %1, %2;" : "=r"(ph_peer1) : "r"(l1), "r"(r_));
        asm("mapa.shared::cluster.u32 %0, %1, %2;" : "=r"(pm_peer0) : "r"(mb_loc0), "r"(r_));
        asm("mapa.shared::cluster.u32 %0, %1, %2;" : "=r"(pm_peer1) : "r"(mb_loc1), "r"(r_));
    }

    const float* gxb = GX + (size_t)b * T_ * G_;
    float* outb      = out + (size_t)b * T_ * H_;
    float gxv = 0.0f;
    float cst = 0.0f;
    int ph0 = 0, ph1 = 0;

    asm volatile("barrier.cluster.arrive.aligned;" ::: "memory");
    asm volatile("barrier.cluster.wait.aligned;" ::: "memory");

    for (int t = 0; t < T_; t++) {
        // tile gate: wait until GEMM finished m-tile (tc, b) = all 4 n-CTAs
        if ((t & 127) == 0) {
            if (tid == 0) {
                const int fidx = (t >> 7) * 32 + b;
                unsigned v;
                do {
                    asm volatile("ld.global.acquire.gpu.u32 %0, [%1];"
                                 : "=r"(v) : "l"((const unsigned*)&g_flag[fidx]) : "memory");
                    if (v < 4u) __nanosleep(128);
                } while (v < 4u);
            }
            __syncthreads();
            if (p == 0) gxv = __ldg(&gxb[(size_t)t * G_ + grow]);
        }

        const int cb = t & 1, nb = cb ^ 1;
        const ulonglong2* h2 = (const ulonglong2*)hbuf[cb];

        u64 acc0 = pk2(0.0f, 0.0f), acc1 = pk2(0.0f, 0.0f);
#pragma unroll
        for (int m = 0; m < 8; m++) {
            ulonglong2 hh = h2[p + 2 * ((base + m) & 15)];
            fma2(acc0, hh.x, wa[m]);
            fma2(acc1, hh.y, wb[m]);
        }
        if (t > 0) {
            uint32_t mb = cb ? mb_loc1 : mb_loc0;
            int par = cb ? ph1 : ph0;
            asm volatile(
                "{\n\t.reg .pred P;\n\t"
                "WL%=:\n\t"
                "mbarrier.try_wait.parity.acquire.cluster.shared::cta.b64 P, [%0], %1, 0x989680;\n\t"
                "@P bra WD%=;\n\t"
                "bra WL%=;\n\t"
                "WD%=:\n\t}"
                :: "r"(mb), "r"(par) : "memory");
            if (cb) ph1 ^= 1; else ph0 ^= 1;
            if (tid == 0)
                asm volatile("mbarrier.arrive.expect_tx.shared.b64 _, [%0], 256;"
                             :: "r"(mb) : "memory");
        }
#pragma unroll
        for (int m = 8; m < 16; m++) {
            ulonglong2 hh = h2[p + 2 * ((base + m) & 15)];
            fma2(acc0, hh.x, wa[m]);
            fma2(acc1, hh.y, wb[m]);
        }
        float2 u0 = upk2(acc0), u1 = upk2(acc1);
        float s = (u0.x + u0.y) + (u1.x + u1.y);
        s += __shfl_xor_sync(0xffffffffu, s, 1);

        if (p == 0) {
            float g = s + gxv;
            acts[rl] = (q == 2) ? fast_tanh(g) : fast_sigmoid(g);
            // prefetch next step only if it stays inside the current tile
            if (((t + 1) & 127) != 0)
                gxv = __ldg(&gxb[(size_t)(t + 1) * G_ + grow]);
        }
        __syncthreads();

        if (tid < 64) {
            float ig = acts[tid];
            float fg = acts[64 + tid];
            float gg = acts[128 + tid];
            float og = acts[192 + tid];
            cst = fg * cst + ig * gg;
            float hv = og * fast_tanh(cst);
            const int hid = (int)rank * 64 + tid;
            hbuf[nb][hid] = hv;
            {
                uint32_t pa = nb ? ph_peer1 : ph_peer0;
                uint32_t pm = nb ? pm_peer1 : pm_peer0;
                asm volatile(
                    "st.async.shared::cluster.mbarrier::complete_tx::bytes.b32 [%0], %1, [%2];"
                    :: "r"(pa), "r"(__float_as_uint(hv)), "r"(pm) : "memory");
            }
            outb[(size_t)t * H_ + hid] = hv;
            if (t == T_ - 1) {
                hn[b * H_ + hid] = hv;
                cn[b * H_ + hid] = cst;
            }
        }
        __syncthreads();
    }
}

// ---------------------------------------------------------------------------
extern "C" void kernel_launch(void* const* d_in, const int* in_sizes, int n_in,
                              void* d_out, int out_size)
{
    const float* x   = (const float*)d_in[0];
    const float* Wih = (const float*)d_in[1];
    const float* Whh = (const float*)d_in[2];
    const float* bih = (const float*)d_in[3];
    const float* bhh = (const float*)d_in[4];
    float* out = (float*)d_out;

    float* gx = nullptr;
    cudaGetSymbolAddress((void**)&gx, g_gx);
    __nv_bfloat16* A2 = nullptr;
    cudaGetSymbolAddress((void**)&A2, g_A2);
    __nv_bfloat16* B2 = nullptr;
    cudaGetSymbolAddress((void**)&B2, g_B2);

    cudaFuncSetAttribute(gemm_mma_x, cudaFuncAttributeMaxDynamicSharedMemorySize, 65536);

    // main-stream prologue: converts + flag reset
    convert_split2<<<(B_ * T_ * (D_ / 4) + 255) / 256, 256>>>(x, A2, B_ * T_);
    convert_split2<<<(G_ * (D_ / 4) + 255) / 256, 256>>>(Wih, B2, G_);
    reset_flags<<<1, 256>>>();

    // fork: GEMM on side stream, recurrence on main stream (flag-gated)
    cudaStream_t s2;
    cudaStreamCreateWithFlags(&s2, cudaStreamNonBlocking);
    cudaEvent_t e0, e1;
    cudaEventCreateWithFlags(&e0, cudaEventDisableTiming);
    cudaEventCreateWithFlags(&e1, cudaEventDisableTiming);

    cudaEventRecord(e0, 0);
    cudaStreamWaitEvent(s2, e0, 0);

    dim3 grid(4, 256);
    gemm_mma_x<<<grid, 256, 65536, s2>>>(A2, B2, bih, bhh, gx);
    cudaEventRecord(e1, s2);

    float* hn = out + (size_t)B_ * T_ * H_;
    float* cn = hn + (size_t)B_ * H_;
    lstm_rec4<<<B_ * 2, 512>>>(gx, Whh, out, hn, cn);

    // join side stream back into the main stream before capture ends
    cudaStreamWaitEvent(0, e1, 0);
}

// round 10
// speedup vs baseline: 1.8702x; 1.0642x over previous
#include <cuda_runtime.h>
#include <cuda_bf16.h>
#include <cstdint>

// LSTM: B=32, T=1024, D=1024, H=128  (gates 4H=512, order i,f,g,o)
// out layout: [B*T*H floats][h_n: B*H][c_n: B*H]

#define B_ 32
#define T_ 1024
#define D_ 1024
#define H_ 128
#define G_ 512
#define GEMM_CTAS 168   // (148 - 64 rec SMs) * 2 CTAs/SM -> GEMM can never starve rec

typedef unsigned long long u64;

__device__ __forceinline__ u64 pk2(float x, float y) {
    u64 r;
    asm("mov.b64 %0, {%1, %2};" : "=l"(r)
        : "r"(__float_as_uint(x)), "r"(__float_as_uint(y)));
    return r;
}
__device__ __forceinline__ float2 upk2(u64 v) {
    unsigned lo, hi;
    asm("mov.b64 {%0, %1}, %2;" : "=r"(lo), "=r"(hi) : "l"(v));
    return make_float2(__uint_as_float(lo), __uint_as_float(hi));
}
__device__ __forceinline__ void fma2(u64 &c, u64 a, u64 b) {
    asm("fma.rn.f32x2 %0, %1, %2, %0;" : "+l"(c) : "l"(a), "l"(b));
}
__device__ __forceinline__ float fast_sigmoid(float x) {
    return 1.0f / (1.0f + __expf(-x));
}
__device__ __forceinline__ float fast_tanh(float x) {
    return 1.0f - 2.0f / (__expf(2.0f * x) + 1.0f);
}
__device__ __forceinline__ uint32_t smem_u32(const void* p) {
    uint32_t a;
    asm("{ .reg .u64 t; cvta.to.shared.u64 t, %1; cvt.u32.u64 %0, t; }"
        : "=r"(a) : "l"(p));
    return a;
}
__device__ __forceinline__ void cp16(uint32_t dst, const void* src) {
    asm volatile("cp.async.cg.shared.global [%0], [%1], 16;"
                 :: "r"(dst), "l"(src));
}
__device__ __forceinline__ void ldsm4(uint32_t* r, uint32_t addr) {
    asm volatile("ldmatrix.sync.aligned.m8n8.x4.shared.b16 {%0,%1,%2,%3}, [%4];"
                 : "=r"(r[0]), "=r"(r[1]), "=r"(r[2]), "=r"(r[3]) : "r"(addr));
}
__device__ __forceinline__ void mma16816(float* d, const uint32_t* a,
                                         uint32_t b0, uint32_t b1) {
    asm volatile(
        "mma.sync.aligned.m16n8k16.row.col.f32.bf16.bf16.f32 "
        "{%0,%1,%2,%3}, {%4,%5,%6,%7}, {%8,%9}, {%0,%1,%2,%3};"
        : "+f"(d[0]), "+f"(d[1]), "+f"(d[2]), "+f"(d[3])
        : "r"(a[0]), "r"(a[1]), "r"(a[2]), "r"(a[3]), "r"(b0), "r"(b1));
}

// Scratch (__device__ globals: allocation-free)
__device__ float g_gx[(size_t)B_ * T_ * G_];                 // 64 MB
__device__ __nv_bfloat16 g_A2[(size_t)B_ * T_ * 2048];       // 128 MB  [hi|mid]
__device__ __nv_bfloat16 g_B2[(size_t)G_ * 2048];            // 2 MB    [hi|mid]
__device__ int g_flag[256];   // per m-tile completion counters (target 4)

__global__ void reset_flags() { g_flag[threadIdx.x] = 0; }

// ---------------------------------------------------------------------------
// fp32 -> 2-way bf16 split: hi = rn(x), mid = rn(x - hi); x ~= hi+mid (2^-17)
// ---------------------------------------------------------------------------
__global__ void convert_split2(const float* __restrict__ X,
                               __nv_bfloat16* __restrict__ OUT, int rows)
{
    size_t i = (size_t)blockIdx.x * blockDim.x + threadIdx.x;
    size_t total = (size_t)rows * (D_ / 4);
    if (i >= total) return;
    float4 v = ((const float4*)X)[i];
    size_t m  = i >> 8;
    int   k4  = (int)(i & 255);

    float xs[4] = {v.x, v.y, v.z, v.w};
    __nv_bfloat16 hi[4], md[4];
#pragma unroll
    for (int c = 0; c < 4; c++) {
        hi[c] = __float2bfloat16(xs[c]);
        float r1 = xs[c] - __bfloat162float(hi[c]);
        md[c] = __float2bfloat16(r1);
    }

    __nv_bfloat162* dh = (__nv_bfloat162*)(OUT + m * 2048 + k4 * 4);
    __nv_bfloat162* dm = (__nv_bfloat162*)(OUT + m * 2048 + 1024 + k4 * 4);
    dh[0] = __halves2bfloat162(hi[0], hi[1]);
    dh[1] = __halves2bfloat162(hi[2], hi[3]);
    dm[0] = __halves2bfloat162(md[0], md[1]);
    dm[1] = __halves2bfloat162(md[2], md[3]);
}

// ---------------------------------------------------------------------------
// PERSISTENT bf16 mma.sync GEMM, 3 phases (h,h)(h,m)(m,h).
// Exactly GEMM_CTAS CTAs (2/SM on 84 SMs) loop over 1024 tiles in tc-major
// order, so the recurrence's 64 SMs are structurally never starved.
// Each m-tile's 4 n-CTAs bump g_flag[y] on completion.
// ---------------------------------------------------------------------------
__global__ __launch_bounds__(256, 2) void gemm_mma_x(
    const __nv_bfloat16* __restrict__ A2, const __nv_bfloat16* __restrict__ B2,
    const float* __restrict__ b1, const float* __restrict__ b2,
    float* __restrict__ GX)
{
    extern __shared__ char smraw[];
    const uint32_t sbase = smem_u32(smraw);

    const int tid = threadIdx.x;
    const int wid = tid >> 5, lid = tid & 31;
    const int wm  = wid >> 2, wn = wid & 3;
    const int mat = lid >> 3, rin = lid & 7;
    const uint32_t aBase = sbase +
        (uint32_t)((((wm * 8 + (mat & 1)) * 8) + (mat >> 1)) * 128 + rin * 16);
    const uint32_t bBase = sbase + 16384 +
        (uint32_t)((((wn * 4 + (mat & 1)) * 8) + (mat >> 1)) * 128 + rin * 16);

    for (int tile = blockIdx.x; tile < 1024; tile += gridDim.x) {
        const int y  = tile >> 2;            // m-tile index, tc-major
        const int n0 = (tile & 3) * 128;
        const int bb = y & 31, tc = y >> 5;
        const int m0 = bb * 1024 + tc * 128;

        const char* Ab = (const char*)A2 + (size_t)m0 * 4096;
        const char* Bb = (const char*)B2 + (size_t)n0 * 4096;

        float acc[4][4][4];
#pragma unroll
        for (int i = 0; i < 4; i++)
#pragma unroll
            for (int j = 0; j < 4; j++)
#pragma unroll
                for (int r = 0; r < 4; r++) acc[i][j][r] = 0.0f;

#define ISSUE(kt, st)                                                          \
    do {                                                                       \
        const int ph_ = (kt) >> 4, kk_ = (kt) & 15;                            \
        const int aoff_ = ((ph_ == 2) ? 2048 : 0) + kk_ * 128;                 \
        const int boff_ = ((ph_ == 1) ? 2048 : 0) + kk_ * 128;                 \
        uint32_t dA = sbase + (st) * 32768;                                    \
        uint32_t dB = dA + 16384;                                              \
        _Pragma("unroll")                                                      \
        for (int it = 0; it < 4; it++) {                                       \
            int id = tid + it * 256;                                           \
            int mm = id >> 3, kg = id & 7;                                     \
            uint32_t doff = (uint32_t)((((mm >> 3) * 8) + kg) * 128 + (mm & 7) * 16); \
            cp16(dA + doff, Ab + (size_t)mm * 4096 + aoff_ + kg * 16);         \
            cp16(dB + doff, Bb + (size_t)mm * 4096 + boff_ + kg * 16);         \
        }                                                                      \
        asm volatile("cp.async.commit_group;" ::: "memory");                   \
    } while (0)

        ISSUE(0, 0);

        const int NKT = 48;
        for (int kt = 0; kt < NKT; kt++) {
            const int st = kt & 1;
            if (kt + 1 < NKT) {
                ISSUE(kt + 1, st ^ 1);
                asm volatile("cp.async.wait_group 1;" ::: "memory");
            } else {
                asm volatile("cp.async.wait_group 0;" ::: "memory");
            }
            __syncthreads();

            const uint32_t aS = aBase + st * 32768;
            const uint32_t bS = bBase + st * 32768;
#pragma unroll
            for (int ks = 0; ks < 4; ks++) {
                uint32_t af[4][4], bf[2][4];
#pragma unroll
                for (int i = 0; i < 4; i++)
                    ldsm4(af[i], aS + i * 2048 + ks * 256);
#pragma unroll
                for (int jp = 0; jp < 2; jp++)
                    ldsm4(bf[jp], bS + jp * 2048 + ks * 256);
#pragma unroll
                for (int i = 0; i < 4; i++)
#pragma unroll
                    for (int j = 0; j < 4; j++)
                        mma16816(acc[i][j], af[i],
                                 bf[j >> 1][j & 1], bf[j >> 1][2 + (j & 1)]);
            }
            __syncthreads();
        }

        // Epilogue: bias + store fp32, then signal tile completion
        const int mrow = lid >> 2;
        const int ncol = 2 * (lid & 3);
        float2 bj[4];
#pragma unroll
        for (int j = 0; j < 4; j++) {
            int n = n0 + wn * 32 + j * 8 + ncol;
            bj[j].x = b1[n] + b2[n];
            bj[j].y = b1[n + 1] + b2[n + 1];
        }
#pragma unroll
        for (int i = 0; i < 4; i++) {
            int r0 = m0 + wm * 64 + i * 16 + mrow;
#pragma unroll
            for (int j = 0; j < 4; j++) {
                int n = n0 + wn * 32 + j * 8 + ncol;
                float2 v0 = make_float2(acc[i][j][0] + bj[j].x, acc[i][j][1] + bj[j].y);
                float2 v1 = make_float2(acc[i][j][2] + bj[j].x, acc[i][j][3] + bj[j].y);
                *(float2*)&GX[(size_t)r0 * G_ + n]        = v0;
                *(float2*)&GX[(size_t)(r0 + 8) * G_ + n]  = v1;
            }
        }
        __threadfence();
        __syncthreads();
        if (tid == 0) atomicAdd(&g_flag[y], 1);
    }
}

// ---------------------------------------------------------------------------
// Recurrence v4 (unchanged): per-128-step tile gating on g_flag,
// boundary-safe gx prefetch, st.async cluster h-exchange.
// ---------------------------------------------------------------------------
__global__ __launch_bounds__(512, 1) __cluster_dims__(2, 1, 1)
void lstm_rec4(const float* __restrict__ GX, const float* __restrict__ Wh,
               float* __restrict__ out, float* __restrict__ hn,
               float* __restrict__ cn)
{
    __shared__ __align__(16) float hbuf[2][128];
    __shared__ __align__(16) float acts[256];
    __shared__ __align__(8) unsigned long long mbar[2];

    const int tid = threadIdx.x;
    uint32_t rank;
    asm("mov.u32 %0, %%cluster_ctarank;" : "=r"(rank));
    const int b    = blockIdx.x >> 1;
    const int rl   = tid >> 1;
    const int p    = tid & 1;
    const int q    = rl >> 6;
    const int j    = rl & 63;
    const int grow = q * 128 + (int)rank * 64 + j;
    const int base = (int)rank * 8;

    u64 wa[16], wb[16];
#pragma unroll
    for (int m = 0; m < 16; m++) {
        int c = p + 2 * ((base + m) & 15);
        float4 w = *(const float4*)&Wh[(size_t)grow * H_ + c * 4];
        wa[m] = pk2(w.x, w.y);
        wb[m] = pk2(w.z, w.w);
    }

    if (tid < 128) { hbuf[0][tid] = 0.0f; hbuf[1][tid] = 0.0f; }
    uint32_t mb_loc0 = smem_u32(&mbar[0]);
    uint32_t mb_loc1 = smem_u32(&mbar[1]);
    if (tid == 0) {
        asm volatile("mbarrier.init.shared.b64 [%0], 1;" :: "r"(mb_loc0) : "memory");
        asm volatile("mbarrier.init.shared.b64 [%0], 1;" :: "r"(mb_loc1) : "memory");
        asm volatile("mbarrier.arrive.expect_tx.shared.b64 _, [%0], 256;" :: "r"(mb_loc0) : "memory");
        asm volatile("mbarrier.arrive.expect_tx.shared.b64 _, [%0], 256;" :: "r"(mb_loc1) : "memory");
    }

    uint32_t ph_peer0, ph_peer1, pm_peer0, pm_peer1;
    {
        const uint32_t r_ = rank ^ 1u;
        int hid = (int)rank * 64 + (tid & 63);
        uint32_t l0 = smem_u32(&hbuf[0][hid]);
        uint32_t l1 = smem_u32(&hbuf[1][hid]);
        asm("mapa.shared::cluster.u32 %0, %1, %2;" : "=r"(ph_peer0) : "r"(l0), "r"(r_));
        asm("mapa.shared::cluster.u32 %0, %1, %2;" : "=r"(ph_peer1) : "r"(l1), "r"(r_));
        asm("mapa.shared::cluster.u32 %0, %1, %2;" : "=r"(pm_peer0) : "r"(mb_loc0), "r"(r_));
        asm("mapa.shared::cluster.u32 %0, %1, %2;" : "=r"(pm_peer1) : "r"(mb_loc1), "r"(r_));
    }

    const float* gxb = GX + (size_t)b * T_ * G_;
    float* outb      = out + (size_t)b * T_ * H_;
    float gxv = 0.0f;
    float cst = 0.0f;
    int ph0 = 0, ph1 = 0;

    asm volatile("barrier.cluster.arrive.aligned;" ::: "memory");
    asm volatile("barrier.cluster.wait.aligned;" ::: "memory");

    for (int t = 0; t < T_; t++) {
        if ((t & 127) == 0) {
            if (tid == 0) {
                const int fidx = (t >> 7) * 32 + b;
                unsigned v;
                do {
                    asm volatile("ld.global.acquire.gpu.u32 %0, [%1];"
                                 : "=r"(v) : "l"((const unsigned*)&g_flag[fidx]) : "memory");
                    if (v < 4u) __nanosleep(128);
                } while (v < 4u);
            }
            __syncthreads();
            if (p == 0) gxv = __ldg(&gxb[(size_t)t * G_ + grow]);
        }

        const int cb = t & 1, nb = cb ^ 1;
        const ulonglong2* h2 = (const ulonglong2*)hbuf[cb];

        u64 acc0 = pk2(0.0f, 0.0f), acc1 = pk2(0.0f, 0.0f);
#pragma unroll
        for (int m = 0; m < 8; m++) {
            ulonglong2 hh = h2[p + 2 * ((base + m) & 15)];
            fma2(acc0, hh.x, wa[m]);
            fma2(acc1, hh.y, wb[m]);
        }
        if (t > 0) {
            uint32_t mb = cb ? mb_loc1 : mb_loc0;
            int par = cb ? ph1 : ph0;
            asm volatile(
                "{\n\t.reg .pred P;\n\t"
                "WL%=:\n\t"
                "mbarrier.try_wait.parity.acquire.cluster.shared::cta.b64 P, [%0], %1, 0x989680;\n\t"
                "@P bra WD%=;\n\t"
                "bra WL%=;\n\t"
                "WD%=:\n\t}"
                :: "r"(mb), "r"(par) : "memory");
            if (cb) ph1 ^= 1; else ph0 ^= 1;
            if (tid == 0)
                asm volatile("mbarrier.arrive.expect_tx.shared.b64 _, [%0], 256;"
                             :: "r"(mb) : "memory");
        }
#pragma unroll
        for (int m = 8; m < 16; m++) {
            ulonglong2 hh = h2[p + 2 * ((base + m) & 15)];
            fma2(acc0, hh.x, wa[m]);
            fma2(acc1, hh.y, wb[m]);
        }
        float2 u0 = upk2(acc0), u1 = upk2(acc1);
        float s = (u0.x + u0.y) + (u1.x + u1.y);
        s += __shfl_xor_sync(0xffffffffu, s, 1);

        if (p == 0) {
            float g = s + gxv;
            acts[rl] = (q == 2) ? fast_tanh(g) : fast_sigmoid(g);
            if (((t + 1) & 127) != 0)
                gxv = __ldg(&gxb[(size_t)(t + 1) * G_ + grow]);
        }
        __syncthreads();

        if (tid < 64) {
            float ig = acts[tid];
            float fg = acts[64 + tid];
            float gg = acts[128 + tid];
            float og = acts[192 + tid];
            cst = fg * cst + ig * gg;
            float hv = og * fast_tanh(cst);
            const int hid = (int)rank * 64 + tid;
            hbuf[nb][hid] = hv;
            {
                uint32_t pa = nb ? ph_peer1 : ph_peer0;
                uint32_t pm = nb ? pm_peer1 : pm_peer0;
                asm volatile(
                    "st.async.shared::cluster.mbarrier::complete_tx::bytes.b32 [%0], %1, [%2];"
                    :: "r"(pa), "r"(__float_as_uint(hv)), "r"(pm) : "memory");
            }
            outb[(size_t)t * H_ + hid] = hv;
            if (t == T_ - 1) {
                hn[b * H_ + hid] = hv;
                cn[b * H_ + hid] = cst;
            }
        }
        __syncthreads();
    }
}

// ---------------------------------------------------------------------------
extern "C" void kernel_launch(void* const* d_in, const int* in_sizes, int n_in,
                              void* d_out, int out_size)
{
    const float* x   = (const float*)d_in[0];
    const float* Wih = (const float*)d_in[1];
    const float* Whh = (const float*)d_in[2];
    const float* bih = (const float*)d_in[3];
    const float* bhh = (const float*)d_in[4];
    float* out = (float*)d_out;

    float* gx = nullptr;
    cudaGetSymbolAddress((void**)&gx, g_gx);
    __nv_bfloat16* A2 = nullptr;
    cudaGetSymbolAddress((void**)&A2, g_A2);
    __nv_bfloat16* B2 = nullptr;
    cudaGetSymbolAddress((void**)&B2, g_B2);

    cudaFuncSetAttribute(gemm_mma_x, cudaFuncAttributeMaxDynamicSharedMemorySize, 65536);

    cudaStream_t s2;
    cudaStreamCreateWithFlags(&s2, cudaStreamNonBlocking);
    cudaEvent_t e0, e1;
    cudaEventCreateWithFlags(&e0, cudaEventDisableTiming);
    cudaEventCreateWithFlags(&e1, cudaEventDisableTiming);

    // main: reset flags, THEN fork (event before rec launch — rec spins on flags)
    reset_flags<<<1, 256>>>();
    cudaEventRecord(e0, 0);
    cudaStreamWaitEvent(s2, e0, 0);

    // side stream: converts + persistent GEMM (168 CTAs = 84 SMs max)
    convert_split2<<<(B_ * T_ * (D_ / 4) + 255) / 256, 256, 0, s2>>>(x, A2, B_ * T_);
    convert_split2<<<(G_ * (D_ / 4) + 255) / 256, 256, 0, s2>>>(Wih, B2, G_);
    gemm_mma_x<<<GEMM_CTAS, 256, 65536, s2>>>(A2, B2, bih, bhh, gx);
    cudaEventRecord(e1, s2);

    // main: recurrence launches immediately, gated on flags per 128-step tile
    float* hn = out + (size_t)B_ * T_ * H_;
    float* cn = hn + (size_t)B_ * H_;
    lstm_rec4<<<B_ * 2, 512>>>(gx, Whh, out, hn, cn);

    // join side stream back into the main stream before capture ends
    cudaStreamWaitEvent(0, e1, 0);
}

// round 11
// speedup vs baseline: 2.1576x; 1.1537x over previous
#include <cuda_runtime.h>
#include <cuda_bf16.h>
#include <cstdint>

// LSTM: B=32, T=1024, D=1024, H=128  (gates 4H=512, order i,f,g,o)
// out layout: [B*T*H floats][h_n: B*H][c_n: B*H]

#define B_ 32
#define T_ 1024
#define D_ 1024
#define H_ 128
#define G_ 512
#define GEMM_CTAS 84      // 1 CTA/SM (144KB smem) on the 84 SMs the rec leaves free
#define STAGE_BYTES 49152 // A 16KB + B 32KB per stage, 3 stages

typedef unsigned long long u64;

__device__ __forceinline__ u64 pk2(float x, float y) {
    u64 r;
    asm("mov.b64 %0, {%1, %2};" : "=l"(r)
        : "r"(__float_as_uint(x)), "r"(__float_as_uint(y)));
    return r;
}
__device__ __forceinline__ float2 upk2(u64 v) {
    unsigned lo, hi;
    asm("mov.b64 {%0, %1}, %2;" : "=r"(lo), "=r"(hi) : "l"(v));
    return make_float2(__uint_as_float(lo), __uint_as_float(hi));
}
__device__ __forceinline__ void fma2(u64 &c, u64 a, u64 b) {
    asm("fma.rn.f32x2 %0, %1, %2, %0;" : "+l"(c) : "l"(a), "l"(b));
}
__device__ __forceinline__ float fast_sigmoid(float x) {
    return 1.0f / (1.0f + __expf(-x));
}
__device__ __forceinline__ float fast_tanh(float x) {
    return 1.0f - 2.0f / (__expf(2.0f * x) + 1.0f);
}
__device__ __forceinline__ uint32_t smem_u32(const void* p) {
    uint32_t a;
    asm("{ .reg .u64 t; cvta.to.shared.u64 t, %1; cvt.u32.u64 %0, t; }"
        : "=r"(a) : "l"(p));
    return a;
}
__device__ __forceinline__ void cp16(uint32_t dst, const void* src) {
    asm volatile("cp.async.cg.shared.global [%0], [%1], 16;"
                 :: "r"(dst), "l"(src));
}
__device__ __forceinline__ void ldsm4(uint32_t* r, uint32_t addr) {
    asm volatile("ldmatrix.sync.aligned.m8n8.x4.shared.b16 {%0,%1,%2,%3}, [%4];"
                 : "=r"(r[0]), "=r"(r[1]), "=r"(r[2]), "=r"(r[3]) : "r"(addr));
}
__device__ __forceinline__ void mma16816(float* d, const uint32_t* a,
                                         uint32_t b0, uint32_t b1) {
    asm volatile(
        "mma.sync.aligned.m16n8k16.row.col.f32.bf16.bf16.f32 "
        "{%0,%1,%2,%3}, {%4,%5,%6,%7}, {%8,%9}, {%0,%1,%2,%3};"
        : "+f"(d[0]), "+f"(d[1]), "+f"(d[2]), "+f"(d[3])
        : "r"(a[0]), "r"(a[1]), "r"(a[2]), "r"(a[3]), "r"(b0), "r"(b1));
}

// Scratch (__device__ globals: allocation-free)
__device__ float g_gx[(size_t)B_ * T_ * G_];                 // 64 MB
__device__ __nv_bfloat16 g_A2[(size_t)B_ * T_ * 2048];       // 128 MB  [hi|mid]
__device__ __nv_bfloat16 g_B2[(size_t)G_ * 2048];            // 2 MB    [hi|mid]
__device__ int g_flag[256];   // per m-tile completion counters (target 2)

__global__ void reset_flags() { g_flag[threadIdx.x] = 0; }

// ---------------------------------------------------------------------------
// fp32 -> 2-way bf16 split: hi = rn(x), mid = rn(x - hi); x ~= hi+mid (2^-17)
// ---------------------------------------------------------------------------
__global__ void convert_split2(const float* __restrict__ X,
                               __nv_bfloat16* __restrict__ OUT, int rows)
{
    size_t i = (size_t)blockIdx.x * blockDim.x + threadIdx.x;
    size_t total = (size_t)rows * (D_ / 4);
    if (i >= total) return;
    float4 v = ((const float4*)X)[i];
    size_t m  = i >> 8;
    int   k4  = (int)(i & 255);

    float xs[4] = {v.x, v.y, v.z, v.w};
    __nv_bfloat16 hi[4], md[4];
#pragma unroll
    for (int c = 0; c < 4; c++) {
        hi[c] = __float2bfloat16(xs[c]);
        float r1 = xs[c] - __bfloat162float(hi[c]);
        md[c] = __float2bfloat16(r1);
    }

    __nv_bfloat162* dh = (__nv_bfloat162*)(OUT + m * 2048 + k4 * 4);
    __nv_bfloat162* dm = (__nv_bfloat162*)(OUT + m * 2048 + 1024 + k4 * 4);
    dh[0] = __halves2bfloat162(hi[0], hi[1]);
    dh[1] = __halves2bfloat162(hi[2], hi[3]);
    dm[0] = __halves2bfloat162(md[0], md[1]);
    dm[1] = __halves2bfloat162(md[2], md[3]);
}

// ---------------------------------------------------------------------------
// PERSISTENT bf16 mma.sync GEMM, 3 phases (h,h)(h,m)(m,h).
// CTA tile 128x256 (halves smem crossbar traffic per MAC vs 128x128),
// 8 warps @ 64x64, 3-stage cp.async with ONE syncthreads per k-tile,
// 1 CTA/SM (144KB smem). 512 tiles tc-major; 2 n-CTAs bump g_flag[y].
// ---------------------------------------------------------------------------
__global__ __launch_bounds__(256, 1) void gemm_mma_x(
    const __nv_bfloat16* __restrict__ A2, const __nv_bfloat16* __restrict__ B2,
    const float* __restrict__ b1, const float* __restrict__ b2,
    float* __restrict__ GX)
{
    extern __shared__ char smraw[];
    const uint32_t sbase = smem_u32(smraw);

    const int tid = threadIdx.x;
    const int wid = tid >> 5, lid = tid & 31;
    const int wm  = wid >> 2, wn = wid & 3;     // 2 x 4 warp grid, 64x64 tiles
    const int mat = lid >> 3, rin = lid & 7;
    const uint32_t aOff = (uint32_t)((((wm * 8 + (mat & 1)) * 8) + (mat >> 1)) * 128 + rin * 16);
    const uint32_t bOff = 16384u +
        (uint32_t)((((wn * 8 + (mat & 1)) * 8) + (mat >> 1)) * 128 + rin * 16);

    for (int tile = blockIdx.x; tile < 512; tile += gridDim.x) {
        const int y  = tile >> 1;            // m-tile index, tc-major
        const int n0 = (tile & 1) * 256;
        const int bb = y & 31, tc = y >> 5;
        const int m0 = bb * 1024 + tc * 128;

        const char* Ab = (const char*)A2 + (size_t)m0 * 4096;
        const char* Bb = (const char*)B2 + (size_t)n0 * 4096;

        float acc[4][8][4];
#pragma unroll
        for (int i = 0; i < 4; i++)
#pragma unroll
            for (int j = 0; j < 8; j++)
#pragma unroll
                for (int r = 0; r < 4; r++) acc[i][j][r] = 0.0f;

        // Stage fill: A 1024 granules (4/thread) + B 2048 granules (8/thread)
#define ISSUE(kt, st)                                                          \
    do {                                                                       \
        const int ph_ = (kt) >> 4, kk_ = (kt) & 15;                            \
        const int aoff_ = ((ph_ == 2) ? 2048 : 0) + kk_ * 128;                 \
        const int boff_ = ((ph_ == 1) ? 2048 : 0) + kk_ * 128;                 \
        uint32_t dA = sbase + (st) * STAGE_BYTES;                              \
        uint32_t dB = dA + 16384;                                              \
        _Pragma("unroll")                                                      \
        for (int it = 0; it < 4; it++) {                                       \
            int id = tid + it * 256;                                           \
            int mm = id >> 3, kg = id & 7;                                     \
            uint32_t doff = (uint32_t)((((mm >> 3) * 8) + kg) * 128 + (mm & 7) * 16); \
            cp16(dA + doff, Ab + (size_t)mm * 4096 + aoff_ + kg * 16);         \
        }                                                                      \
        _Pragma("unroll")                                                      \
        for (int it = 0; it < 8; it++) {                                       \
            int id = tid + it * 256;                                           \
            int mm = id >> 3, kg = id & 7;                                     \
            uint32_t doff = (uint32_t)((((mm >> 3) * 8) + kg) * 128 + (mm & 7) * 16); \
            cp16(dB + doff, Bb + (size_t)mm * 4096 + boff_ + kg * 16);         \
        }                                                                      \
        asm volatile("cp.async.commit_group;" ::: "memory");                   \
    } while (0)

        ISSUE(0, 0);
        ISSUE(1, 1);

        const int NKT = 48;
        for (int kt = 0; kt < NKT; kt++) {
            const int st = kt % 3;
            if (kt + 1 < NKT) {
                asm volatile("cp.async.wait_group 1;" ::: "memory");
            } else {
                asm volatile("cp.async.wait_group 0;" ::: "memory");
            }
            __syncthreads();   // single barrier: cp visibility + overwrite guard

            const uint32_t aS = sbase + st * STAGE_BYTES + aOff;
            const uint32_t bS = sbase + st * STAGE_BYTES + bOff;
#pragma unroll
            for (int ks = 0; ks < 4; ks++) {
                uint32_t af[4][4], bf[4][4];
#pragma unroll
                for (int i = 0; i < 4; i++)
                    ldsm4(af[i], aS + i * 2048 + ks * 256);
#pragma unroll
                for (int jp = 0; jp < 4; jp++)
                    ldsm4(bf[jp], bS + jp * 2048 + ks * 256);
#pragma unroll
                for (int i = 0; i < 4; i++)
#pragma unroll
                    for (int j = 0; j < 8; j++)
                        mma16816(acc[i][j], af[i],
                                 bf[j >> 1][j & 1], bf[j >> 1][2 + (j & 1)]);
            }
            if (kt + 2 < NKT) ISSUE(kt + 2, (kt + 2) % 3);
        }

        // Epilogue: bias + store fp32, then signal tile completion
        const int mrow = lid >> 2;
        const int ncol = 2 * (lid & 3);
        float2 bj[8];
#pragma unroll
        for (int j = 0; j < 8; j++) {
            int n = n0 + wn * 64 + j * 8 + ncol;
            bj[j].x = b1[n] + b2[n];
            bj[j].y = b1[n + 1] + b2[n + 1];
        }
#pragma unroll
        for (int i = 0; i < 4; i++) {
            int r0 = m0 + wm * 64 + i * 16 + mrow;
#pragma unroll
            for (int j = 0; j < 8; j++) {
                int n = n0 + wn * 64 + j * 8 + ncol;
                float2 v0 = make_float2(acc[i][j][0] + bj[j].x, acc[i][j][1] + bj[j].y);
                float2 v1 = make_float2(acc[i][j][2] + bj[j].x, acc[i][j][3] + bj[j].y);
                *(float2*)&GX[(size_t)r0 * G_ + n]        = v0;
                *(float2*)&GX[(size_t)(r0 + 8) * G_ + n]  = v1;
            }
        }
        __threadfence();
        __syncthreads();
        if (tid == 0) atomicAdd(&g_flag[y], 1);
    }
}

// ---------------------------------------------------------------------------
// Recurrence v4: per-128-step tile gating on g_flag (target 2),
// boundary-safe gx prefetch, st.async cluster h-exchange.
// ---------------------------------------------------------------------------
__global__ __launch_bounds__(512, 1) __cluster_dims__(2, 1, 1)
void lstm_rec4(const float* __restrict__ GX, const float* __restrict__ Wh,
               float* __restrict__ out, float* __restrict__ hn,
               float* __restrict__ cn)
{
    __shared__ __align__(16) float hbuf[2][128];
    __shared__ __align__(16) float acts[256];
    __shared__ __align__(8) unsigned long long mbar[2];

    const int tid = threadIdx.x;
    uint32_t rank;
    asm("mov.u32 %0, %%cluster_ctarank;" : "=r"(rank));
    const int b    = blockIdx.x >> 1;
    const int rl   = tid >> 1;
    const int p    = tid & 1;
    const int q    = rl >> 6;
    const int j    = rl & 63;
    const int grow = q * 128 + (int)rank * 64 + j;
    const int base = (int)rank * 8;

    u64 wa[16], wb[16];
#pragma unroll
    for (int m = 0; m < 16; m++) {
        int c = p + 2 * ((base + m) & 15);
        float4 w = *(const float4*)&Wh[(size_t)grow * H_ + c * 4];
        wa[m] = pk2(w.x, w.y);
        wb[m] = pk2(w.z, w.w);
    }

    if (tid < 128) { hbuf[0][tid] = 0.0f; hbuf[1][tid] = 0.0f; }
    uint32_t mb_loc0 = smem_u32(&mbar[0]);
    uint32_t mb_loc1 = smem_u32(&mbar[1]);
    if (tid == 0) {
        asm volatile("mbarrier.init.shared.b64 [%0], 1;" :: "r"(mb_loc0) : "memory");
        asm volatile("mbarrier.init.shared.b64 [%0], 1;" :: "r"(mb_loc1) : "memory");
        asm volatile("mbarrier.arrive.expect_tx.shared.b64 _, [%0], 256;" :: "r"(mb_loc0) : "memory");
        asm volatile("mbarrier.arrive.expect_tx.shared.b64 _, [%0], 256;" :: "r"(mb_loc1) : "memory");
    }

    uint32_t ph_peer0, ph_peer1, pm_peer0, pm_peer1;
    {
        const uint32_t r_ = rank ^ 1u;
        int hid = (int)rank * 64 + (tid & 63);
        uint32_t l0 = smem_u32(&hbuf[0][hid]);
        uint32_t l1 = smem_u32(&hbuf[1][hid]);
        asm("mapa.shared::cluster.u32 %0, %1, %2;" : "=r"(ph_peer0) : "r"(l0), "r"(r_));
        asm("mapa.shared::cluster.u32 %0, %1, %2;" : "=r"(ph_peer1) : "r"(l1), "r"(r_));
        asm("mapa.shared::cluster.u32 %0, %1, %2;" : "=r"(pm_peer0) : "r"(mb_loc0), "r"(r_));
        asm("mapa.shared::cluster.u32 %0, %1, %2;" : "=r"(pm_peer1) : "r"(mb_loc1), "r"(r_));
    }

    const float* gxb = GX + (size_t)b * T_ * G_;
    float* outb      = out + (size_t)b * T_ * H_;
    float gxv = 0.0f;
    float cst = 0.0f;
    int ph0 = 0, ph1 = 0;

    asm volatile("barrier.cluster.arrive.aligned;" ::: "memory");
    asm volatile("barrier.cluster.wait.aligned;" ::: "memory");

    for (int t = 0; t < T_; t++) {
        if ((t & 127) == 0) {
            if (tid == 0) {
                const int fidx = (t >> 7) * 32 + b;
                unsigned v;
                do {
                    asm volatile("ld.global.acquire.gpu.u32 %0, [%1];"
                                 : "=r"(v) : "l"((const unsigned*)&g_flag[fidx]) : "memory");
                    if (v < 2u) __nanosleep(128);
                } while (v < 2u);
            }
            __syncthreads();
            if (p == 0) gxv = __ldg(&gxb[(size_t)t * G_ + grow]);
        }

        const int cb = t & 1, nb = cb ^ 1;
        const ulonglong2* h2 = (const ulonglong2*)hbuf[cb];

        u64 acc0 = pk2(0.0f, 0.0f), acc1 = pk2(0.0f, 0.0f);
#pragma unroll
        for (int m = 0; m < 8; m++) {
            ulonglong2 hh = h2[p + 2 * ((base + m) & 15)];
            fma2(acc0, hh.x, wa[m]);
            fma2(acc1, hh.y, wb[m]);
        }
        if (t > 0) {
            uint32_t mb = cb ? mb_loc1 : mb_loc0;
            int par = cb ? ph1 : ph0;
            asm volatile(
                "{\n\t.reg .pred P;\n\t"
                "WL%=:\n\t"
                "mbarrier.try_wait.parity.acquire.cluster.shared::cta.b64 P, [%0], %1, 0x989680;\n\t"
                "@P bra WD%=;\n\t"
                "bra WL%=;\n\t"
                "WD%=:\n\t}"
                :: "r"(mb), "r"(par) : "memory");
            if (cb) ph1 ^= 1; else ph0 ^= 1;
            if (tid == 0)
                asm volatile("mbarrier.arrive.expect_tx.shared.b64 _, [%0], 256;"
                             :: "r"(mb) : "memory");
        }
#pragma unroll
        for (int m = 8; m < 16; m++) {
            ulonglong2 hh = h2[p + 2 * ((base + m) & 15)];
            fma2(acc0, hh.x, wa[m]);
            fma2(acc1, hh.y, wb[m]);
        }
        float2 u0 = upk2(acc0), u1 = upk2(acc1);
        float s = (u0.x + u0.y) + (u1.x + u1.y);
        s += __shfl_xor_sync(0xffffffffu, s, 1);

        if (p == 0) {
            float g = s + gxv;
            acts[rl] = (q == 2) ? fast_tanh(g) : fast_sigmoid(g);
            if (((t + 1) & 127) != 0)
                gxv = __ldg(&gxb[(size_t)(t + 1) * G_ + grow]);
        }
        __syncthreads();

        if (tid < 64) {
            float ig = acts[tid];
            float fg = acts[64 + tid];
            float gg = acts[128 + tid];
            float og = acts[192 + tid];
            cst = fg * cst + ig * gg;
            float hv = og * fast_tanh(cst);
            const int hid = (int)rank * 64 + tid;
            hbuf[nb][hid] = hv;
            {
                uint32_t pa = nb ? ph_peer1 : ph_peer0;
                uint32_t pm = nb ? pm_peer1 : pm_peer0;
                asm volatile(
                    "st.async.shared::cluster.mbarrier::complete_tx::bytes.b32 [%0], %1, [%2];"
                    :: "r"(pa), "r"(__float_as_uint(hv)), "r"(pm) : "memory");
            }
            outb[(size_t)t * H_ + hid] = hv;
            if (t == T_ - 1) {
                hn[b * H_ + hid] = hv;
                cn[b * H_ + hid] = cst;
            }
        }
        __syncthreads();
    }
}

// ---------------------------------------------------------------------------
extern "C" void kernel_launch(void* const* d_in, const int* in_sizes, int n_in,
                              void* d_out, int out_size)
{
    const float* x   = (const float*)d_in[0];
    const float* Wih = (const float*)d_in[1];
    const float* Whh = (const float*)d_in[2];
    const float* bih = (const float*)d_in[3];
    const float* bhh = (const float*)d_in[4];
    float* out = (float*)d_out;

    float* gx = nullptr;
    cudaGetSymbolAddress((void**)&gx, g_gx);
    __nv_bfloat16* A2 = nullptr;
    cudaGetSymbolAddress((void**)&A2, g_A2);
    __nv_bfloat16* B2 = nullptr;
    cudaGetSymbolAddress((void**)&B2, g_B2);

    cudaFuncSetAttribute(gemm_mma_x, cudaFuncAttributeMaxDynamicSharedMemorySize,
                         3 * STAGE_BYTES);

    cudaStream_t s2;
    cudaStreamCreateWithFlags(&s2, cudaStreamNonBlocking);
    cudaEvent_t e0, e1;
    cudaEventCreateWithFlags(&e0, cudaEventDisableTiming);
    cudaEventCreateWithFlags(&e1, cudaEventDisableTiming);

    // main: converts (full chip, before the rec occupies its SMs) + flag reset
    convert_split2<<<(B_ * T_ * (D_ / 4) + 255) / 256, 256>>>(x, A2, B_ * T_);
    convert_split2<<<(G_ * (D_ / 4) + 255) / 256, 256>>>(Wih, B2, G_);
    reset_flags<<<1, 256>>>();

    cudaEventRecord(e0, 0);
    cudaStreamWaitEvent(s2, e0, 0);

    // side stream: persistent GEMM (84 CTAs, 1/SM via 144KB smem)
    gemm_mma_x<<<GEMM_CTAS, 256, 3 * STAGE_BYTES, s2>>>(A2, B2, bih, bhh, gx);
    cudaEventRecord(e1, s2);

    // main: recurrence, gated on flags per 128-step tile
    float* hn = out + (size_t)B_ * T_ * H_;
    float* cn = hn + (size_t)B_ * H_;
    lstm_rec4<<<B_ * 2, 512>>>(gx, Whh, out, hn, cn);

    // join side stream back into the main stream before capture ends
    cudaStreamWaitEvent(0, e1, 0);
}